// round 12
// baseline (speedup 1.0000x reference)
#include <cuda_runtime.h>
#include <cuda_bf16.h>
#include <math.h>
#include <stdint.h>

#define NROWS 32768
#define C 128
#define H 8
#define NC 64
#define SUBT 4
#define NT (NROWS / 128)
#define KP 136                 // plane row pitch in bf16 elems (272B)
#define PLANEB 34816           // bytes per 128-row plane
#define PLANEE 17408           // elems per plane
#define IMG2 69632             // hi+lo image bytes
#define PITCHF 132

typedef __nv_bfloat16 bf16;

// ---------------- scratch ----------------
__device__ float    g_M_part[NC * H * C * C];        // [c][h][m][i] fp32 partials of phi^T src
__device__ float    g_kss_part[NC * H * C];
__device__ char     g_Mimg[(size_t)H * IMG2];        // M[h] split images (row m, col i)
__device__ char     g_ktvImg[(size_t)H * IMG2];      // KtV[h] split images (row d, col m)
__device__ float    g_kss[H * C];
__device__ char     g_WcombImg[IMG2];                // Wcomb split image (row o, col i)
__device__ float    g_bcomb[C];
__device__ char     g_qimg[(size_t)NT * IMG2];
__device__ char     g_simg[(size_t)NT * IMG2];
__device__ char     g_wimg[(size_t)24 * IMG2];       // Wq[8],Wk[8],Wv[8]

// ---------------- low-level ----------------
__device__ __forceinline__ uint32_t smem_u32(const void* p) {
    return (uint32_t)__cvta_generic_to_shared(p);
}
__device__ __forceinline__ void ldm4(uint32_t r[4], const bf16* p) {
    uint32_t a = smem_u32(p);
    asm volatile("ldmatrix.sync.aligned.m8n8.x4.shared.b16 {%0,%1,%2,%3}, [%4];"
                 : "=r"(r[0]), "=r"(r[1]), "=r"(r[2]), "=r"(r[3]) : "r"(a));
}
__device__ __forceinline__ void ldm4t(uint32_t r[4], const bf16* p) {
    uint32_t a = smem_u32(p);
    asm volatile("ldmatrix.sync.aligned.m8n8.x4.trans.shared.b16 {%0,%1,%2,%3}, [%4];"
                 : "=r"(r[0]), "=r"(r[1]), "=r"(r[2]), "=r"(r[3]) : "r"(a));
}
__device__ __forceinline__ void mma_bf16(float d[4], const uint32_t a[4],
                                         uint32_t b0, uint32_t b1) {
    asm volatile(
        "mma.sync.aligned.m16n8k16.row.col.f32.bf16.bf16.f32 "
        "{%0,%1,%2,%3},{%4,%5,%6,%7},{%8,%9},{%0,%1,%2,%3};"
        : "+f"(d[0]), "+f"(d[1]), "+f"(d[2]), "+f"(d[3])
        : "r"(a[0]), "r"(a[1]), "r"(a[2]), "r"(a[3]), "r"(b0), "r"(b1));
}
__device__ __forceinline__ uint32_t bf2pack(bf16 x, bf16 y) {
    return (uint32_t)__bfloat16_as_ushort(x) | ((uint32_t)__bfloat16_as_ushort(y) << 16);
}
__device__ __forceinline__ void cpa16(uint32_t d, const void* s) {
    asm volatile("cp.async.cg.shared.global [%0], [%1], 16;" ::"r"(d), "l"(s));
}
#define CP_COMMIT() asm volatile("cp.async.commit_group;" ::: "memory")
#define CP_WAIT0()  asm volatile("cp.async.wait_group 0;" ::: "memory")
#define CP_WAIT1()  asm volatile("cp.async.wait_group 1;" ::: "memory")

// 256-thread async 68KB image copy
__device__ __forceinline__ void copy_img_async(char* dst, const char* __restrict__ src) {
    uint32_t d = smem_u32(dst);
    int tid = threadIdx.x;
#pragma unroll
    for (int it = 0; it < 17; it++) {
        int i = (tid + it * 256) * 16;
        cpa16(d + i, src + i);
    }
}

// transposed split store (plane row = feature m, plane col = token r); works gmem/smem
__device__ __forceinline__ void storeT_p(char* p, int m, int r, float x) {
    bf16 h = __float2bfloat16(x);
    int ob = m * 272 + r * 2;
    *(bf16*)(p + ob) = h;
    *(bf16*)(p + PLANEB + ob) = __float2bfloat16(x - __bfloat162float(h));
}

// full-width warp GEMM: rows [mrow,mrow+16) x 128 cols, K=128, split-bf16 3-pass
__device__ __forceinline__ void wgemm(float acc[16][4], const char* pA, const char* pB,
                                      int mrow) {
    const bf16* Ahi = (const bf16*)pA;
    const bf16* Alo = Ahi + PLANEE;
    const bf16* Bhi = (const bf16*)pB;
    const bf16* Blo = Bhi + PLANEE;
    int lane = threadIdx.x & 31;
    int lr = lane & 15, lc = lane >> 4;
#pragma unroll
    for (int kt = 0; kt < 8; kt++) {
        int aoff = (mrow + lr) * KP + kt * 16 + lc * 8;
        uint32_t ah[4], al[4];
        ldm4(ah, Ahi + aoff);
        ldm4(al, Alo + aoff);
#pragma unroll
        for (int nt = 0; nt < 8; nt++) {
            int boff = (nt * 16 + lr) * KP + kt * 16 + lc * 8;
            uint32_t bh[4], bl[4];
            ldm4(bh, Bhi + boff);
            ldm4(bl, Blo + boff);
            mma_bf16(acc[nt * 2], ah, bh[0], bh[2]);
            mma_bf16(acc[nt * 2], ah, bl[0], bl[2]);
            mma_bf16(acc[nt * 2], al, bh[0], bh[2]);
            mma_bf16(acc[nt * 2 + 1], ah, bh[1], bh[3]);
            mma_bf16(acc[nt * 2 + 1], ah, bl[1], bl[3]);
            mma_bf16(acc[nt * 2 + 1], al, bh[1], bh[3]);
        }
    }
}

// GEMM with A fragments already in registers (ph/pl[kt][0..3]); B split image in smem
__device__ __forceinline__ void wgemm_regA(float acc[16][4],
                                           const uint32_t ph[8][4], const uint32_t pl[8][4],
                                           const char* pB) {
    const bf16* Bhi = (const bf16*)pB;
    const bf16* Blo = Bhi + PLANEE;
    int lane = threadIdx.x & 31;
    int lr = lane & 15, lc = lane >> 4;
#pragma unroll
    for (int kt = 0; kt < 8; kt++) {
#pragma unroll
        for (int nt = 0; nt < 8; nt++) {
            int boff = (nt * 16 + lr) * KP + kt * 16 + lc * 8;
            uint32_t bh[4], bl[4];
            ldm4(bh, Bhi + boff);
            ldm4(bl, Blo + boff);
            mma_bf16(acc[nt * 2], ph[kt], bh[0], bh[2]);
            mma_bf16(acc[nt * 2], ph[kt], bl[0], bl[2]);
            mma_bf16(acc[nt * 2], pl[kt], bh[0], bh[2]);
            mma_bf16(acc[nt * 2 + 1], ph[kt], bh[1], bh[3]);
            mma_bf16(acc[nt * 2 + 1], ph[kt], bl[1], bl[3]);
            mma_bf16(acc[nt * 2 + 1], pl[kt], bh[1], bh[3]);
        }
    }
}

// trans-B warp GEMM: acc[m][i] += sum_r A[m][r] * S[r][i]
__device__ __forceinline__ void wgemm_trans(float acc[16][4], const char* pA, const char* pS,
                                            int mrow) {
    const bf16* Ahi = (const bf16*)pA;
    const bf16* Alo = Ahi + PLANEE;
    const bf16* Shi = (const bf16*)pS;
    const bf16* Slo = Shi + PLANEE;
    int lane = threadIdx.x & 31;
    int lr = lane & 15, lc = lane >> 4;
#pragma unroll
    for (int kt = 0; kt < 8; kt++) {
        int aoff = (mrow + lr) * KP + kt * 16 + lc * 8;
        uint32_t ah[4], al[4];
        ldm4(ah, Ahi + aoff);
        ldm4(al, Alo + aoff);
#pragma unroll
        for (int nt = 0; nt < 8; nt++) {
            int boff = (kt * 16 + lr) * KP + nt * 16 + lc * 8;
            uint32_t bh[4], bl[4];
            ldm4t(bh, Shi + boff);
            ldm4t(bl, Slo + boff);
            mma_bf16(acc[nt * 2], ah, bh[0], bh[1]);
            mma_bf16(acc[nt * 2], ah, bl[0], bl[1]);
            mma_bf16(acc[nt * 2], al, bh[0], bh[1]);
            mma_bf16(acc[nt * 2 + 1], ah, bh[2], bh[3]);
            mma_bf16(acc[nt * 2 + 1], ah, bl[2], bl[3]);
            mma_bf16(acc[nt * 2 + 1], al, bh[2], bh[3]);
        }
    }
}

#define ZERO16x4(a)                                   \
    _Pragma("unroll") for (int _f = 0; _f < 16; _f++) \
        { a[_f][0] = 0.f; a[_f][1] = 0.f; a[_f][2] = 0.f; a[_f][3] = 0.f; }

// ---------------- kprep: fp32 -> split-bf16 images ----------------
__global__ void __launch_bounds__(256, 1)
kprep(const float* __restrict__ q, const float* __restrict__ src,
      const float* __restrict__ Wq, const float* __restrict__ Wk,
      const float* __restrict__ Wv) {
    int b = blockIdx.x;
    const float* g;
    char* dst;
    if (b < NT) { g = q + (size_t)b * 128 * C; dst = g_qimg + (size_t)b * IMG2; }
    else if (b < 2 * NT) { g = src + (size_t)(b - NT) * 128 * C; dst = g_simg + (size_t)(b - NT) * IMG2; }
    else {
        int i = b - 2 * NT;
        int mat = i >> 3, h = i & 7;
        g = ((mat == 0) ? Wq : (mat == 1) ? Wk : Wv) + (size_t)h * C * C;
        dst = g_wimg + (size_t)i * IMG2;
    }
    char* lo = dst + PLANEB;
    int tid = threadIdx.x;
#pragma unroll
    for (int it = 0; it < 8; it++) {
        int idx = tid + it * 256;
        int row = idx >> 4, c0 = (idx & 15) << 3;
        float4 a = *(const float4*)(g + (size_t)row * C + c0);
        float4 bb = *(const float4*)(g + (size_t)row * C + c0 + 4);
        float v8[8] = {a.x, a.y, a.z, a.w, bb.x, bb.y, bb.z, bb.w};
        uint32_t hw[4], lw[4];
#pragma unroll
        for (int i2 = 0; i2 < 4; i2++) {
            bf16 h0 = __float2bfloat16(v8[2 * i2]);
            bf16 h1 = __float2bfloat16(v8[2 * i2 + 1]);
            bf16 l0 = __float2bfloat16(v8[2 * i2] - __bfloat162float(h0));
            bf16 l1 = __float2bfloat16(v8[2 * i2 + 1] - __bfloat162float(h1));
            hw[i2] = bf2pack(h0, h1);
            lw[i2] = bf2pack(l0, l1);
        }
        int ob = row * 272 + c0 * 2;
        *(uint4*)(dst + ob) = make_uint4(hw[0], hw[1], hw[2], hw[3]);
        *(uint4*)(lo + ob) = make_uint4(lw[0], lw[1], lw[2], lw[3]);
    }
}

// ---------------- kw_comb: combined vss weights -> split image ----------------
__global__ void __launch_bounds__(256, 1)
kw_comb(const float* __restrict__ Wv, const float* __restrict__ Wvb,
        const float* __restrict__ vmap, const float* __restrict__ vmapb) {
    extern __shared__ char smraw[];
    float* sWb = (float*)smraw;
    int tid = threadIdx.x, lane = tid & 31, w = tid >> 5;
#pragma unroll
    for (int it = 0; it < 64; it++) {
        int idx = tid + it * 256;
        int d = idx >> 7, i = idx & 127;
        float s = 0.f;
#pragma unroll
        for (int h = 0; h < H; h++) s += Wv[((size_t)h * C + d) * C + i];
        sWb[d * PITCHF + i] = s * 0.125f;
    }
    __syncthreads();
    int o = blockIdx.x * 8 + w;
    float r[4] = {0.f, 0.f, 0.f, 0.f};
    for (int d = 0; d < 128; d++) {
        float vm = vmap[(size_t)o * C + d];
#pragma unroll
        for (int k = 0; k < 4; k++) r[k] += vm * sWb[d * PITCHF + lane + 32 * k];
    }
#pragma unroll
    for (int k = 0; k < 4; k++) storeT_p(g_WcombImg, o, lane + 32 * k, r[k]);
    if (blockIdx.x == 0 && tid < 128) {
        float s = 0.f;
        for (int d = 0; d < 128; d++) {
            float bv = 0.f;
#pragma unroll
            for (int h = 0; h < H; h++) bv += Wvb[h * C + d];
            s += vmap[(size_t)tid * C + d] * (bv * 0.125f);
        }
        g_bcomb[tid] = s + vmapb[tid];
    }
}

// ---------------- K2: per (chunk, head): phi_k -> M += phi^T src, kss ----------------
#define K2_BIA (3 * IMG2)
__global__ void __launch_bounds__(256, 1)
k2_kv(const float* __restrict__ Wkb, const float* __restrict__ ns) {
    extern __shared__ char sm[];
    char* pA = sm;               // src image
    char* pB = sm + IMG2;        // Wk (static all subtiles)
    char* pP = sm + 2 * IMG2;    // phi^T
    float* sBk = (float*)(sm + K2_BIA);
    float* sKss = sBk + 128;
    int chunk = blockIdx.x, h = blockIdx.y;
    int tid = threadIdx.x, w = tid >> 5, lane = tid & 31;
    int mrow = w * 16;
    int grA = mrow + (lane >> 2), grB = grA + 8;
    float ids = 1.f / (fabsf(ns[0]) + 1e-6f);

    if (tid < 128) {
        sBk[tid] = Wkb[h * C + tid];
        sKss[tid] = 0.f;
    }
    float accM[16][4];
    ZERO16x4(accM);

    copy_img_async(pB, g_wimg + (size_t)(8 + h) * IMG2);
    copy_img_async(pA, g_simg + (size_t)(chunk * SUBT) * IMG2);
    CP_COMMIT();

    for (int s = 0; s < SUBT; s++) {
        if (s > 0) {
            __syncthreads();
            copy_img_async(pA, g_simg + (size_t)(chunk * SUBT + s) * IMG2);
            CP_COMMIT();
        }
        CP_WAIT0();
        __syncthreads();

        float acc[16][4];
        ZERO16x4(acc);
        wgemm(acc, pA, pB, mrow);

        float xs[16][4], s1a = 0.f, s2a = 0.f, s1b = 0.f, s2b = 0.f;
#pragma unroll
        for (int f = 0; f < 16; f++) {
            int c = ((f >> 1) << 4) + ((f & 1) << 3) + ((lane & 3) << 1);
            float b0 = sBk[c], b1 = sBk[c + 1];
            float x;
            x = (fmaxf(acc[f][0] + b0, 0.f) + 1e-6f) * ids; x *= x; xs[f][0] = x; s1a += x; s2a += x * x;
            x = (fmaxf(acc[f][1] + b1, 0.f) + 1e-6f) * ids; x *= x; xs[f][1] = x; s1a += x; s2a += x * x;
            x = (fmaxf(acc[f][2] + b0, 0.f) + 1e-6f) * ids; x *= x; xs[f][2] = x; s1b += x; s2b += x * x;
            x = (fmaxf(acc[f][3] + b1, 0.f) + 1e-6f) * ids; x *= x; xs[f][3] = x; s1b += x; s2b += x * x;
        }
        s1a += __shfl_xor_sync(~0u, s1a, 1); s1a += __shfl_xor_sync(~0u, s1a, 2);
        s2a += __shfl_xor_sync(~0u, s2a, 1); s2a += __shfl_xor_sync(~0u, s2a, 2);
        s1b += __shfl_xor_sync(~0u, s1b, 1); s1b += __shfl_xor_sync(~0u, s1b, 2);
        s2b += __shfl_xor_sync(~0u, s2b, 1); s2b += __shfl_xor_sync(~0u, s2b, 2);
        float sca = sqrtf(s1a) / (sqrtf(s2a) + 1e-8f);
        float scb = sqrtf(s1b) / (sqrtf(s2b) + 1e-8f);

        // kss column partials straight from registers (sum over this warp's 16 rows)
#pragma unroll
        for (int f = 0; f < 16; f++) {
            float v0 = xs[f][0] * sca + xs[f][2] * scb;
            float v1 = xs[f][1] * sca + xs[f][3] * scb;
            v0 += __shfl_xor_sync(~0u, v0, 4);
            v0 += __shfl_xor_sync(~0u, v0, 8);
            v0 += __shfl_xor_sync(~0u, v0, 16);
            v1 += __shfl_xor_sync(~0u, v1, 4);
            v1 += __shfl_xor_sync(~0u, v1, 8);
            v1 += __shfl_xor_sync(~0u, v1, 16);
            if (lane < 4) {
                int c = ((f >> 1) << 4) + ((f & 1) << 3) + (lane << 1);
                atomicAdd(&sKss[c], v0);
                atomicAdd(&sKss[c + 1], v1);
            }
        }

#pragma unroll
        for (int f = 0; f < 16; f++) {
            int c = ((f >> 1) << 4) + ((f & 1) << 3) + ((lane & 3) << 1);
            storeT_p(pP, c, grA, xs[f][0] * sca);
            storeT_p(pP, c + 1, grA, xs[f][1] * sca);
            storeT_p(pP, c, grB, xs[f][2] * scb);
            storeT_p(pP, c + 1, grB, xs[f][3] * scb);
        }
        __syncthreads();   // phi^T fully visible

        wgemm_trans(accM, pP, pA, mrow);
    }

    size_t base = ((size_t)(chunk * H + h)) * C * C;
#pragma unroll
    for (int f = 0; f < 16; f++) {
        int c = ((f >> 1) << 4) + ((f & 1) << 3) + ((lane & 3) << 1);
        *(float2*)(g_M_part + base + (size_t)grA * C + c) = make_float2(accM[f][0], accM[f][1]);
        *(float2*)(g_M_part + base + (size_t)grB * C + c) = make_float2(accM[f][2], accM[f][3]);
    }
    __syncthreads();   // all sKss atomics done
    if (tid < 128)
        g_kss_part[(size_t)(chunk * H + h) * C + tid] = sKss[tid];
}

// ---------------- K2b: reduce M parts -> split image; reduce kss ----------------
__global__ void k2b_reduce() {
    int i = blockIdx.x * blockDim.x + threadIdx.x;
    int h = i >> 14, rem = i & 16383, m = rem >> 7, ii = rem & 127;
    float s = 0.f;
#pragma unroll 8
    for (int c = 0; c < NC; c++) s += g_M_part[(size_t)c * (H * C * C) + i];
    storeT_p(g_Mimg + (size_t)h * IMG2, m, ii, s);
    if (i < H * C) {
        float s2 = 0.f;
#pragma unroll 8
        for (int c = 0; c < NC; c++) s2 += g_kss_part[(size_t)c * (H * C) + i];
        g_kss[i] = s2;
    }
}

// ---------------- K2c: KtV[h] = M[h] @ Wv[h]^T + kss⊗b -> split image [d][m] ----------------
__global__ void __launch_bounds__(256, 1)
k2c_ktv(const float* __restrict__ Wvb) {
    extern __shared__ char sm[];
    char* pA = sm;
    char* pB = sm + IMG2;
    float* sKss = (float*)(sm + 2 * IMG2);
    float* sBv = sKss + 128;
    int h = blockIdx.x;
    int tid = threadIdx.x, w = tid >> 5, lane = tid & 31;
    int mrow = w * 16;
    int grA = mrow + (lane >> 2), grB = grA + 8;

    copy_img_async(pA, g_Mimg + (size_t)h * IMG2);
    copy_img_async(pB, g_wimg + (size_t)(16 + h) * IMG2);
    CP_COMMIT();
    if (tid < 128) {
        sKss[tid] = g_kss[h * C + tid];
        sBv[tid] = Wvb[h * C + tid];
    }
    CP_WAIT0();
    __syncthreads();

    float acc[16][4];
    ZERO16x4(acc);
    wgemm(acc, pA, pB, mrow);   // acc[m][d] = sum_i M[m][i] Wv[d][i]
    float kssA = sKss[grA], kssB = sKss[grB];
    char* img = g_ktvImg + (size_t)h * IMG2;
#pragma unroll
    for (int f = 0; f < 16; f++) {
        int c = ((f >> 1) << 4) + ((f & 1) << 3) + ((lane & 3) << 1);
        storeT_p(img, c, grA, acc[f][0] + kssA * sBv[c]);
        storeT_p(img, c + 1, grA, acc[f][1] + kssA * sBv[c + 1]);
        storeT_p(img, c, grB, acc[f][2] + kssB * sBv[c]);
        storeT_p(img, c + 1, grB, acc[f][3] + kssB * sBv[c + 1]);
    }
}

// ---------------- KQ: fused phi_q + numerator + comb + epilogue ----------------
#define KQ_MISC (3 * IMG2)
__global__ void __launch_bounds__(256, 1)
kq_fused(const float* __restrict__ Wqb, const float* __restrict__ ns,
         float* __restrict__ out) {
    extern __shared__ char sm[];
    char* pA = sm;               // q image (persistent), then src (prefetched at h=7)
    char* pB = sm + IMG2;        // Wq[h] (prefetched), then Wcomb (prefetched at h=7)
    char* pC = sm + 2 * IMG2;    // ktv image (prefetched)
    float* sBias = (float*)(sm + KQ_MISC);
    float* sKs = sBias + 128;
    float* sBc = sKs + 128;
    int t = blockIdx.x, n0 = t * 128;
    int tid = threadIdx.x, w = tid >> 5, lane = tid & 31;
    int mrow = w * 16;
    int grA = mrow + (lane >> 2), grB = grA + 8;
    float ids = 1.f / (fabsf(ns[0]) + 1e-6f);

    // group 1: pA + pB(0); group 2: pC(0)
    copy_img_async(pA, g_qimg + (size_t)t * IMG2);
    copy_img_async(pB, g_wimg);
    CP_COMMIT();
    copy_img_async(pC, g_ktvImg);
    CP_COMMIT();
    if (tid < 128) sBc[tid] = g_bcomb[tid];

    float outacc[16][4];
    ZERO16x4(outacc);

    for (int h = 0; h < H; h++) {
        CP_WAIT1();        // pA + pB(h) ready (pC(h) may still be in flight)
        if (tid < 128) {
            sBias[tid] = Wqb[h * C + tid];
            sKs[tid] = g_kss[h * C + tid];
        }
        __syncthreads();

        float acc[16][4];
        ZERO16x4(acc);
        wgemm(acc, pA, pB, mrow);

        float xs[16][4];
        float s1a = 0.f, s2a = 0.f, sda = 0.f, s1b = 0.f, s2b = 0.f, sdb = 0.f;
#pragma unroll
        for (int f = 0; f < 16; f++) {
            int c = ((f >> 1) << 4) + ((f & 1) << 3) + ((lane & 3) << 1);
            float b0 = sBias[c], b1 = sBias[c + 1];
            float k0 = sKs[c], k1 = sKs[c + 1];
            float x;
            x = (fmaxf(acc[f][0] + b0, 0.f) + 1e-6f) * ids; x *= x; xs[f][0] = x; s1a += x; s2a += x * x; sda += x * k0;
            x = (fmaxf(acc[f][1] + b1, 0.f) + 1e-6f) * ids; x *= x; xs[f][1] = x; s1a += x; s2a += x * x; sda += x * k1;
            x = (fmaxf(acc[f][2] + b0, 0.f) + 1e-6f) * ids; x *= x; xs[f][2] = x; s1b += x; s2b += x * x; sdb += x * k0;
            x = (fmaxf(acc[f][3] + b1, 0.f) + 1e-6f) * ids; x *= x; xs[f][3] = x; s1b += x; s2b += x * x; sdb += x * k1;
        }
        s1a += __shfl_xor_sync(~0u, s1a, 1); s1a += __shfl_xor_sync(~0u, s1a, 2);
        s2a += __shfl_xor_sync(~0u, s2a, 1); s2a += __shfl_xor_sync(~0u, s2a, 2);
        sda += __shfl_xor_sync(~0u, sda, 1); sda += __shfl_xor_sync(~0u, sda, 2);
        s1b += __shfl_xor_sync(~0u, s1b, 1); s1b += __shfl_xor_sync(~0u, s1b, 2);
        s2b += __shfl_xor_sync(~0u, s2b, 1); s2b += __shfl_xor_sync(~0u, s2b, 2);
        sdb += __shfl_xor_sync(~0u, sdb, 1); sdb += __shfl_xor_sync(~0u, sdb, 2);
        float sca = sqrtf(s1a) / (sqrtf(s2a) + 1e-8f);
        float scb = sqrtf(s1b) / (sqrtf(s2b) + 1e-8f);
        float denA = 0.125f / (sca * sda + 1e-6f);
        float denB = 0.125f / (scb * sdb + 1e-6f);

        // phi -> A fragments entirely in registers
        uint32_t ph[8][4], pl[8][4];
#pragma unroll
        for (int kt = 0; kt < 8; kt++) {
#pragma unroll
            for (int half = 0; half < 2; half++) {
                int f = 2 * kt + half;
                float v0 = xs[f][0] * sca, v1 = xs[f][1] * sca;
                float v2 = xs[f][2] * scb, v3 = xs[f][3] * scb;
                bf16 h0 = __float2bfloat16(v0), h1 = __float2bfloat16(v1);
                bf16 h2 = __float2bfloat16(v2), h3 = __float2bfloat16(v3);
                ph[kt][half * 2] = bf2pack(h0, h1);       // row rA
                ph[kt][half * 2 + 1] = bf2pack(h2, h3);   // row rB
                pl[kt][half * 2] = bf2pack(__float2bfloat16(v0 - __bfloat162float(h0)),
                                           __float2bfloat16(v1 - __bfloat162float(h1)));
                pl[kt][half * 2 + 1] = bf2pack(__float2bfloat16(v2 - __bfloat162float(h2)),
                                               __float2bfloat16(v3 - __bfloat162float(h3)));
            }
        }

        __syncthreads();   // all warps done reading pB(h); (for h=7: also done with pA/q)
        if (h < 7) copy_img_async(pB, g_wimg + (size_t)(h + 1) * IMG2);
        else       copy_img_async(pB, g_WcombImg);        // comb prefetch in gemm2 slot
        CP_COMMIT();
        CP_WAIT1();        // pC(h) done (pB prefetch may be pending)
        __syncthreads();   // pC visible to all warps

        // numerator GEMM: phi (regs) @ ktv
        ZERO16x4(acc);
        wgemm_regA(acc, ph, pl, pC);
#pragma unroll
        for (int f = 0; f < 16; f++) {
            outacc[f][0] += acc[f][0] * denA;
            outacc[f][1] += acc[f][1] * denA;
            outacc[f][2] += acc[f][2] * denB;
            outacc[f][3] += acc[f][3] * denB;
        }
        __syncthreads();   // all warps done reading pC(h)
        if (h < 7) copy_img_async(pC, g_ktvImg + (size_t)(h + 1) * IMG2);
        else       copy_img_async(pA, g_simg + (size_t)t * IMG2);   // src prefetch
        CP_COMMIT();
    }

    // comb (vss branch) — pA(src) + pB(Wcomb) already prefetched
    CP_WAIT0();
    __syncthreads();
    {
        float acc[16][4];
        ZERO16x4(acc);
        wgemm(acc, pA, pB, mrow);
#pragma unroll
        for (int f = 0; f < 16; f++) {
            int c = ((f >> 1) << 4) + ((f & 1) << 3) + ((lane & 3) << 1);
            outacc[f][0] += acc[f][0] + sBc[c];
            outacc[f][1] += acc[f][1] + sBc[c + 1];
            outacc[f][2] += acc[f][2] + sBc[c];
            outacc[f][3] += acc[f][3] + sBc[c + 1];
        }
    }

    // time coordinate + store
    float ssa = 0.f, ssb = 0.f;
#pragma unroll
    for (int f = 0; f < 16; f++) {
        ssa += outacc[f][0] * outacc[f][0] + outacc[f][1] * outacc[f][1];
        ssb += outacc[f][2] * outacc[f][2] + outacc[f][3] * outacc[f][3];
    }
    ssa += __shfl_xor_sync(~0u, ssa, 1); ssa += __shfl_xor_sync(~0u, ssa, 2);
    ssb += __shfl_xor_sync(~0u, ssb, 1); ssb += __shfl_xor_sync(~0u, ssb, 2);
    float* rowA = out + (size_t)(n0 + grA) * 129;
    float* rowB = out + (size_t)(n0 + grB) * 129;
    if ((lane & 3) == 0) {
        rowA[0] = sqrtf(ssa + 1.0f);
        rowB[0] = sqrtf(ssb + 1.0f);
    }
#pragma unroll
    for (int f = 0; f < 16; f++) {
        int c = ((f >> 1) << 4) + ((f & 1) << 3) + ((lane & 3) << 1);
        rowA[1 + c] = outacc[f][0];
        rowA[2 + c] = outacc[f][1];
        rowB[1 + c] = outacc[f][2];
        rowB[2 + c] = outacc[f][3];
    }
}

// ---------------- launch ----------------
extern "C" void kernel_launch(void* const* d_in, const int* in_sizes, int n_in,
                              void* d_out, int out_size) {
    const float* q     = (const float*)d_in[0];
    const float* src   = (const float*)d_in[1];
    const float* Wq    = (const float*)d_in[2];
    const float* Wqb   = (const float*)d_in[3];
    const float* Wk    = (const float*)d_in[4];
    const float* Wkb   = (const float*)d_in[5];
    const float* Wv    = (const float*)d_in[6];
    const float* Wvb   = (const float*)d_in[7];
    const float* vmap  = (const float*)d_in[8];
    const float* vmapb = (const float*)d_in[9];
    const float* ns    = (const float*)d_in[10];
    float* out = (float*)d_out;

    size_t sm2 = (size_t)3 * IMG2 + 1024;          // ~209.9 KB
    size_t smc = (size_t)2 * IMG2 + 1024;          // ~140.3 KB
    size_t smq = (size_t)3 * IMG2 + 1536;          // ~210.4 KB
    size_t smw = (size_t)128 * PITCHF * 4;         // 67,584 B
    cudaFuncSetAttribute(k2_kv,    cudaFuncAttributeMaxDynamicSharedMemorySize, (int)sm2);
    cudaFuncSetAttribute(k2c_ktv,  cudaFuncAttributeMaxDynamicSharedMemorySize, (int)smc);
    cudaFuncSetAttribute(kq_fused, cudaFuncAttributeMaxDynamicSharedMemorySize, (int)smq);
    cudaFuncSetAttribute(kw_comb,  cudaFuncAttributeMaxDynamicSharedMemorySize, (int)smw);

    kprep<<<2 * NT + 24, 256>>>(q, src, Wq, Wk, Wv);
    kw_comb<<<16, 256, smw>>>(Wv, Wvb, vmap, vmapb);
    k2_kv<<<dim3(NC, H), 256, sm2>>>(Wkb, ns);
    k2b_reduce<<<(H * C * C) / 256, 256>>>();
    k2c_ktv<<<H, 256, smc>>>(Wvb);
    kq_fused<<<NT, 256, smq>>>(Wqb, ns, out);
}

// round 14
// speedup vs baseline: 1.0914x; 1.0914x over previous
#include <cuda_runtime.h>
#include <cuda_bf16.h>
#include <math.h>
#include <stdint.h>

#define NROWS 32768
#define C 128
#define H 8
#define NC 64
#define SUBT 4
#define NT (NROWS / 128)
#define KP 136                 // plane row pitch in bf16 elems (272B)
#define PLANEB 34816           // bytes per 128-row plane
#define PLANEE 17408           // elems per plane
#define IMG2 69632             // hi+lo image bytes
#define PITCHF 132

typedef __nv_bfloat16 bf16;

// ---------------- scratch ----------------
__device__ float    g_M_part[NC * H * C * C];        // [c][h][m][i] fp32 partials of phi^T src
__device__ float    g_kss_part[NC * H * C];
__device__ char     g_Mimg[(size_t)H * IMG2];        // M[h] split images (row m, col i)
__device__ char     g_ktvImg[(size_t)H * IMG2];      // KtV[h] split images (row d, col m)
__device__ float    g_kss[H * C];
__device__ char     g_WcombImg[IMG2];                // Wcomb split image (row o, col i)
__device__ float    g_bcomb[C];
__device__ char     g_qimg[(size_t)NT * IMG2];
__device__ char     g_simg[(size_t)NT * IMG2];
__device__ char     g_wimg[(size_t)24 * IMG2];       // Wq[8],Wk[8],Wv[8]

// ---------------- low-level ----------------
__device__ __forceinline__ uint32_t smem_u32(const void* p) {
    return (uint32_t)__cvta_generic_to_shared(p);
}
__device__ __forceinline__ void ldm4(uint32_t r[4], const bf16* p) {
    uint32_t a = smem_u32(p);
    asm volatile("ldmatrix.sync.aligned.m8n8.x4.shared.b16 {%0,%1,%2,%3}, [%4];"
                 : "=r"(r[0]), "=r"(r[1]), "=r"(r[2]), "=r"(r[3]) : "r"(a));
}
__device__ __forceinline__ void ldm4t(uint32_t r[4], const bf16* p) {
    uint32_t a = smem_u32(p);
    asm volatile("ldmatrix.sync.aligned.m8n8.x4.trans.shared.b16 {%0,%1,%2,%3}, [%4];"
                 : "=r"(r[0]), "=r"(r[1]), "=r"(r[2]), "=r"(r[3]) : "r"(a));
}
__device__ __forceinline__ void mma_bf16(float d[4], const uint32_t a[4],
                                         uint32_t b0, uint32_t b1) {
    asm volatile(
        "mma.sync.aligned.m16n8k16.row.col.f32.bf16.bf16.f32 "
        "{%0,%1,%2,%3},{%4,%5,%6,%7},{%8,%9},{%0,%1,%2,%3};"
        : "+f"(d[0]), "+f"(d[1]), "+f"(d[2]), "+f"(d[3])
        : "r"(a[0]), "r"(a[1]), "r"(a[2]), "r"(a[3]), "r"(b0), "r"(b1));
}
__device__ __forceinline__ uint32_t bf2pack(bf16 x, bf16 y) {
    return (uint32_t)__bfloat16_as_ushort(x) | ((uint32_t)__bfloat16_as_ushort(y) << 16);
}
__device__ __forceinline__ void cpa16(uint32_t d, const void* s) {
    asm volatile("cp.async.cg.shared.global [%0], [%1], 16;" ::"r"(d), "l"(s));
}
#define CP_COMMIT() asm volatile("cp.async.commit_group;" ::: "memory")
#define CP_WAIT0()  asm volatile("cp.async.wait_group 0;" ::: "memory")
#define CP_WAIT1()  asm volatile("cp.async.wait_group 1;" ::: "memory")

// 256-thread async 68KB image copy
__device__ __forceinline__ void copy_img_async(char* dst, const char* __restrict__ src) {
    uint32_t d = smem_u32(dst);
    int tid = threadIdx.x;
#pragma unroll
    for (int it = 0; it < 17; it++) {
        int i = (tid + it * 256) * 16;
        cpa16(d + i, src + i);
    }
}

// transposed split store (plane row = feature m, plane col = token r); works gmem/smem
__device__ __forceinline__ void storeT_p(char* p, int m, int r, float x) {
    bf16 h = __float2bfloat16(x);
    int ob = m * 272 + r * 2;
    *(bf16*)(p + ob) = h;
    *(bf16*)(p + PLANEB + ob) = __float2bfloat16(x - __bfloat162float(h));
}

// full-width warp GEMM: rows [mrow,mrow+16) x 128 cols, K=128, split-bf16 3-pass
__device__ __forceinline__ void wgemm(float acc[16][4], const char* pA, const char* pB,
                                      int mrow) {
    const bf16* Ahi = (const bf16*)pA;
    const bf16* Alo = Ahi + PLANEE;
    const bf16* Bhi = (const bf16*)pB;
    const bf16* Blo = Bhi + PLANEE;
    int lane = threadIdx.x & 31;
    int lr = lane & 15, lc = lane >> 4;
#pragma unroll
    for (int kt = 0; kt < 8; kt++) {
        int aoff = (mrow + lr) * KP + kt * 16 + lc * 8;
        uint32_t ah[4], al[4];
        ldm4(ah, Ahi + aoff);
        ldm4(al, Alo + aoff);
#pragma unroll
        for (int nt = 0; nt < 8; nt++) {
            int boff = (nt * 16 + lr) * KP + kt * 16 + lc * 8;
            uint32_t bh[4], bl[4];
            ldm4(bh, Bhi + boff);
            ldm4(bl, Blo + boff);
            mma_bf16(acc[nt * 2], ah, bh[0], bh[2]);
            mma_bf16(acc[nt * 2], ah, bl[0], bl[2]);
            mma_bf16(acc[nt * 2], al, bh[0], bh[2]);
            mma_bf16(acc[nt * 2 + 1], ah, bh[1], bh[3]);
            mma_bf16(acc[nt * 2 + 1], ah, bl[1], bl[3]);
            mma_bf16(acc[nt * 2 + 1], al, bh[1], bh[3]);
        }
    }
}

// GEMM with A fragments already in registers (ph/pl[kt][0..3]); B split image in smem
__device__ __forceinline__ void wgemm_regA(float acc[16][4],
                                           const uint32_t ph[8][4], const uint32_t pl[8][4],
                                           const char* pB) {
    const bf16* Bhi = (const bf16*)pB;
    const bf16* Blo = Bhi + PLANEE;
    int lane = threadIdx.x & 31;
    int lr = lane & 15, lc = lane >> 4;
#pragma unroll
    for (int kt = 0; kt < 8; kt++) {
#pragma unroll
        for (int nt = 0; nt < 8; nt++) {
            int boff = (nt * 16 + lr) * KP + kt * 16 + lc * 8;
            uint32_t bh[4], bl[4];
            ldm4(bh, Bhi + boff);
            ldm4(bl, Blo + boff);
            mma_bf16(acc[nt * 2], ph[kt], bh[0], bh[2]);
            mma_bf16(acc[nt * 2], ph[kt], bl[0], bl[2]);
            mma_bf16(acc[nt * 2], pl[kt], bh[0], bh[2]);
            mma_bf16(acc[nt * 2 + 1], ph[kt], bh[1], bh[3]);
            mma_bf16(acc[nt * 2 + 1], ph[kt], bl[1], bl[3]);
            mma_bf16(acc[nt * 2 + 1], pl[kt], bh[1], bh[3]);
        }
    }
}

// trans-B warp GEMM: acc[m][i] += sum_r A[m][r] * S[r][i]
__device__ __forceinline__ void wgemm_trans(float acc[16][4], const char* pA, const char* pS,
                                            int mrow) {
    const bf16* Ahi = (const bf16*)pA;
    const bf16* Alo = Ahi + PLANEE;
    const bf16* Shi = (const bf16*)pS;
    const bf16* Slo = Shi + PLANEE;
    int lane = threadIdx.x & 31;
    int lr = lane & 15, lc = lane >> 4;
#pragma unroll
    for (int kt = 0; kt < 8; kt++) {
        int aoff = (mrow + lr) * KP + kt * 16 + lc * 8;
        uint32_t ah[4], al[4];
        ldm4(ah, Ahi + aoff);
        ldm4(al, Alo + aoff);
#pragma unroll
        for (int nt = 0; nt < 8; nt++) {
            int boff = (kt * 16 + lr) * KP + nt * 16 + lc * 8;
            uint32_t bh[4], bl[4];
            ldm4t(bh, Shi + boff);
            ldm4t(bl, Slo + boff);
            mma_bf16(acc[nt * 2], ah, bh[0], bh[1]);
            mma_bf16(acc[nt * 2], ah, bl[0], bl[1]);
            mma_bf16(acc[nt * 2], al, bh[0], bh[1]);
            mma_bf16(acc[nt * 2 + 1], ah, bh[2], bh[3]);
            mma_bf16(acc[nt * 2 + 1], ah, bl[2], bl[3]);
            mma_bf16(acc[nt * 2 + 1], al, bh[2], bh[3]);
        }
    }
}

#define ZERO16x4(a)                                   \
    _Pragma("unroll") for (int _f = 0; _f < 16; _f++) \
        { a[_f][0] = 0.f; a[_f][1] = 0.f; a[_f][2] = 0.f; a[_f][3] = 0.f; }

// ---------------- kprep: fp32 -> split-bf16 images ----------------
__global__ void __launch_bounds__(256, 1)
kprep(const float* __restrict__ q, const float* __restrict__ src,
      const float* __restrict__ Wq, const float* __restrict__ Wk,
      const float* __restrict__ Wv) {
    int b = blockIdx.x;
    const float* g;
    char* dst;
    if (b < NT) { g = q + (size_t)b * 128 * C; dst = g_qimg + (size_t)b * IMG2; }
    else if (b < 2 * NT) { g = src + (size_t)(b - NT) * 128 * C; dst = g_simg + (size_t)(b - NT) * IMG2; }
    else {
        int i = b - 2 * NT;
        int mat = i >> 3, h = i & 7;
        g = ((mat == 0) ? Wq : (mat == 1) ? Wk : Wv) + (size_t)h * C * C;
        dst = g_wimg + (size_t)i * IMG2;
    }
    char* lo = dst + PLANEB;
    int tid = threadIdx.x;
#pragma unroll
    for (int it = 0; it < 8; it++) {
        int idx = tid + it * 256;
        int row = idx >> 4, c0 = (idx & 15) << 3;
        float4 a = *(const float4*)(g + (size_t)row * C + c0);
        float4 bb = *(const float4*)(g + (size_t)row * C + c0 + 4);
        float v8[8] = {a.x, a.y, a.z, a.w, bb.x, bb.y, bb.z, bb.w};
        uint32_t hw[4], lw[4];
#pragma unroll
        for (int i2 = 0; i2 < 4; i2++) {
            bf16 h0 = __float2bfloat16(v8[2 * i2]);
            bf16 h1 = __float2bfloat16(v8[2 * i2 + 1]);
            bf16 l0 = __float2bfloat16(v8[2 * i2] - __bfloat162float(h0));
            bf16 l1 = __float2bfloat16(v8[2 * i2 + 1] - __bfloat162float(h1));
            hw[i2] = bf2pack(h0, h1);
            lw[i2] = bf2pack(l0, l1);
        }
        int ob = row * 272 + c0 * 2;
        *(uint4*)(dst + ob) = make_uint4(hw[0], hw[1], hw[2], hw[3]);
        *(uint4*)(lo + ob) = make_uint4(lw[0], lw[1], lw[2], lw[3]);
    }
}

// ---------------- kw_comb: combined vss weights -> split image ----------------
__global__ void __launch_bounds__(256, 1)
kw_comb(const float* __restrict__ Wv, const float* __restrict__ Wvb,
        const float* __restrict__ vmap, const float* __restrict__ vmapb) {
    extern __shared__ char smraw[];
    float* sWb = (float*)smraw;
    int tid = threadIdx.x, lane = tid & 31, w = tid >> 5;
#pragma unroll
    for (int it = 0; it < 64; it++) {
        int idx = tid + it * 256;
        int d = idx >> 7, i = idx & 127;
        float s = 0.f;
#pragma unroll
        for (int h = 0; h < H; h++) s += Wv[((size_t)h * C + d) * C + i];
        sWb[d * PITCHF + i] = s * 0.125f;
    }
    __syncthreads();
    int o = blockIdx.x * 8 + w;
    float r[4] = {0.f, 0.f, 0.f, 0.f};
    for (int d = 0; d < 128; d++) {
        float vm = vmap[(size_t)o * C + d];
#pragma unroll
        for (int k = 0; k < 4; k++) r[k] += vm * sWb[d * PITCHF + lane + 32 * k];
    }
#pragma unroll
    for (int k = 0; k < 4; k++) storeT_p(g_WcombImg, o, lane + 32 * k, r[k]);
    if (blockIdx.x == 0 && tid < 128) {
        float s = 0.f;
        for (int d = 0; d < 128; d++) {
            float bv = 0.f;
#pragma unroll
            for (int h = 0; h < H; h++) bv += Wvb[h * C + d];
            s += vmap[(size_t)tid * C + d] * (bv * 0.125f);
        }
        g_bcomb[tid] = s + vmapb[tid];
    }
}

// ---------------- K2: per (chunk, head): phi_k -> M += phi^T src, kss (R11 version) ----------------
#define K2_BIA (3 * IMG2)
__global__ void __launch_bounds__(256, 1)
k2_kv(const float* __restrict__ Wkb, const float* __restrict__ ns) {
    extern __shared__ char sm[];
    char* pA = sm;               // src image
    char* pB = sm + IMG2;        // Wk (static all subtiles)
    char* pP = sm + 2 * IMG2;    // phi^T
    float* sBk = (float*)(sm + K2_BIA);
    int chunk = blockIdx.x, h = blockIdx.y;
    int tid = threadIdx.x, w = tid >> 5, lane = tid & 31;
    int mrow = w * 16;
    int grA = mrow + (lane >> 2), grB = grA + 8;
    float ids = 1.f / (fabsf(ns[0]) + 1e-6f);

    if (tid < 128) sBk[tid] = Wkb[h * C + tid];
    float accM[16][4];
    ZERO16x4(accM);
    float kss_loc = 0.f;

    copy_img_async(pB, g_wimg + (size_t)(8 + h) * IMG2);
    copy_img_async(pA, g_simg + (size_t)(chunk * SUBT) * IMG2);
    CP_COMMIT();

    for (int s = 0; s < SUBT; s++) {
        if (s > 0) {
            __syncthreads();
            copy_img_async(pA, g_simg + (size_t)(chunk * SUBT + s) * IMG2);
            CP_COMMIT();
        }
        CP_WAIT0();
        __syncthreads();

        float acc[16][4];
        ZERO16x4(acc);
        wgemm(acc, pA, pB, mrow);

        float xs[16][4], s1a = 0.f, s2a = 0.f, s1b = 0.f, s2b = 0.f;
#pragma unroll
        for (int f = 0; f < 16; f++) {
            int c = ((f >> 1) << 4) + ((f & 1) << 3) + ((lane & 3) << 1);
            float b0 = sBk[c], b1 = sBk[c + 1];
            float x;
            x = (fmaxf(acc[f][0] + b0, 0.f) + 1e-6f) * ids; x *= x; xs[f][0] = x; s1a += x; s2a += x * x;
            x = (fmaxf(acc[f][1] + b1, 0.f) + 1e-6f) * ids; x *= x; xs[f][1] = x; s1a += x; s2a += x * x;
            x = (fmaxf(acc[f][2] + b0, 0.f) + 1e-6f) * ids; x *= x; xs[f][2] = x; s1b += x; s2b += x * x;
            x = (fmaxf(acc[f][3] + b1, 0.f) + 1e-6f) * ids; x *= x; xs[f][3] = x; s1b += x; s2b += x * x;
        }
        s1a += __shfl_xor_sync(~0u, s1a, 1); s1a += __shfl_xor_sync(~0u, s1a, 2);
        s2a += __shfl_xor_sync(~0u, s2a, 1); s2a += __shfl_xor_sync(~0u, s2a, 2);
        s1b += __shfl_xor_sync(~0u, s1b, 1); s1b += __shfl_xor_sync(~0u, s1b, 2);
        s2b += __shfl_xor_sync(~0u, s2b, 1); s2b += __shfl_xor_sync(~0u, s2b, 2);
        float sca = sqrtf(s1a) / (sqrtf(s2a) + 1e-8f);
        float scb = sqrtf(s1b) / (sqrtf(s2b) + 1e-8f);
#pragma unroll
        for (int f = 0; f < 16; f++) {
            int c = ((f >> 1) << 4) + ((f & 1) << 3) + ((lane & 3) << 1);
            storeT_p(pP, c, grA, xs[f][0] * sca);
            storeT_p(pP, c + 1, grA, xs[f][1] * sca);
            storeT_p(pP, c, grB, xs[f][2] * scb);
            storeT_p(pP, c + 1, grB, xs[f][3] * scb);
        }
        __syncthreads();   // phi^T fully visible

        if (tid < 128) {
            float s0 = 0.f;
#pragma unroll 8
            for (int r = 0; r < 128; r++) {
                int ob = tid * 272 + r * 2;
                s0 += __bfloat162float(*(bf16*)(pP + ob)) +
                      __bfloat162float(*(bf16*)(pP + PLANEB + ob));
            }
            kss_loc += s0;
        }
        wgemm_trans(accM, pP, pA, mrow);
    }

    size_t base = ((size_t)(chunk * H + h)) * C * C;
#pragma unroll
    for (int f = 0; f < 16; f++) {
        int c = ((f >> 1) << 4) + ((f & 1) << 3) + ((lane & 3) << 1);
        *(float2*)(g_M_part + base + (size_t)grA * C + c) = make_float2(accM[f][0], accM[f][1]);
        *(float2*)(g_M_part + base + (size_t)grB * C + c) = make_float2(accM[f][2], accM[f][3]);
    }
    if (tid < 128)
        g_kss_part[(size_t)(chunk * H + h) * C + tid] = kss_loc;
}

// ---------------- K2b: reduce M parts -> split image; reduce kss ----------------
__global__ void k2b_reduce() {
    int i = blockIdx.x * blockDim.x + threadIdx.x;
    int h = i >> 14, rem = i & 16383, m = rem >> 7, ii = rem & 127;
    float s = 0.f;
#pragma unroll 8
    for (int c = 0; c < NC; c++) s += g_M_part[(size_t)c * (H * C * C) + i];
    storeT_p(g_Mimg + (size_t)h * IMG2, m, ii, s);
    if (i < H * C) {
        float s2 = 0.f;
#pragma unroll 8
        for (int c = 0; c < NC; c++) s2 += g_kss_part[(size_t)c * (H * C) + i];
        g_kss[i] = s2;
    }
}

// ---------------- K2c: KtV[h] = M[h] @ Wv[h]^T + kss⊗b -> split image [d][m] ----------------
__global__ void __launch_bounds__(256, 1)
k2c_ktv(const float* __restrict__ Wvb) {
    extern __shared__ char sm[];
    char* pA = sm;
    char* pB = sm + IMG2;
    float* sKss = (float*)(sm + 2 * IMG2);
    float* sBv = sKss + 128;
    int h = blockIdx.x;
    int tid = threadIdx.x, w = tid >> 5, lane = tid & 31;
    int mrow = w * 16;
    int grA = mrow + (lane >> 2), grB = grA + 8;

    copy_img_async(pA, g_Mimg + (size_t)h * IMG2);
    copy_img_async(pB, g_wimg + (size_t)(16 + h) * IMG2);
    CP_COMMIT();
    if (tid < 128) {
        sKss[tid] = g_kss[h * C + tid];
        sBv[tid] = Wvb[h * C + tid];
    }
    CP_WAIT0();
    __syncthreads();

    float acc[16][4];
    ZERO16x4(acc);
    wgemm(acc, pA, pB, mrow);   // acc[m][d] = sum_i M[m][i] Wv[d][i]
    float kssA = sKss[grA], kssB = sKss[grB];
    char* img = g_ktvImg + (size_t)h * IMG2;
#pragma unroll
    for (int f = 0; f < 16; f++) {
        int c = ((f >> 1) << 4) + ((f & 1) << 3) + ((lane & 3) << 1);
        storeT_p(img, c, grA, acc[f][0] + kssA * sBv[c]);
        storeT_p(img, c + 1, grA, acc[f][1] + kssA * sBv[c + 1]);
        storeT_p(img, c, grB, acc[f][2] + kssB * sBv[c]);
        storeT_p(img, c + 1, grB, acc[f][3] + kssB * sBv[c + 1]);
    }
}

// ---------------- KQ: fused phi_q + numerator + comb + epilogue ----------------
#define KQ_MISC (3 * IMG2)
__global__ void __launch_bounds__(256, 1)
kq_fused(const float* __restrict__ Wqb, const float* __restrict__ ns,
         float* __restrict__ out) {
    extern __shared__ char sm[];
    char* pA = sm;               // q image (persistent), then src (prefetched at h=7)
    char* pB = sm + IMG2;        // Wq[h] (prefetched), then Wcomb (prefetched at h=7)
    char* pC = sm + 2 * IMG2;    // ktv image (prefetched)
    float* sBias = (float*)(sm + KQ_MISC);
    float* sKs = sBias + 128;
    float* sBc = sKs + 128;
    int t = blockIdx.x, n0 = t * 128;
    int tid = threadIdx.x, w = tid >> 5, lane = tid & 31;
    int mrow = w * 16;
    int grA = mrow + (lane >> 2), grB = grA + 8;
    float ids = 1.f / (fabsf(ns[0]) + 1e-6f);

    // group 1: pA + pB(0); group 2: pC(0)
    copy_img_async(pA, g_qimg + (size_t)t * IMG2);
    copy_img_async(pB, g_wimg);
    CP_COMMIT();
    copy_img_async(pC, g_ktvImg);
    CP_COMMIT();
    if (tid < 128) sBc[tid] = g_bcomb[tid];

    float outacc[16][4];
    ZERO16x4(outacc);

    for (int h = 0; h < H; h++) {
        CP_WAIT1();        // pA + pB(h) ready (pC(h) may still be in flight)
        if (tid < 128) {
            sBias[tid] = Wqb[h * C + tid];
            sKs[tid] = g_kss[h * C + tid];
        }
        __syncthreads();

        float acc[16][4];
        ZERO16x4(acc);
        wgemm(acc, pA, pB, mrow);

        float xs[16][4];
        float s1a = 0.f, s2a = 0.f, sda = 0.f, s1b = 0.f, s2b = 0.f, sdb = 0.f;
#pragma unroll
        for (int f = 0; f < 16; f++) {
            int c = ((f >> 1) << 4) + ((f & 1) << 3) + ((lane & 3) << 1);
            float b0 = sBias[c], b1 = sBias[c + 1];
            float k0 = sKs[c], k1 = sKs[c + 1];
            float x;
            x = (fmaxf(acc[f][0] + b0, 0.f) + 1e-6f) * ids; x *= x; xs[f][0] = x; s1a += x; s2a += x * x; sda += x * k0;
            x = (fmaxf(acc[f][1] + b1, 0.f) + 1e-6f) * ids; x *= x; xs[f][1] = x; s1a += x; s2a += x * x; sda += x * k1;
            x = (fmaxf(acc[f][2] + b0, 0.f) + 1e-6f) * ids; x *= x; xs[f][2] = x; s1b += x; s2b += x * x; sdb += x * k0;
            x = (fmaxf(acc[f][3] + b1, 0.f) + 1e-6f) * ids; x *= x; xs[f][3] = x; s1b += x; s2b += x * x; sdb += x * k1;
        }
        s1a += __shfl_xor_sync(~0u, s1a, 1); s1a += __shfl_xor_sync(~0u, s1a, 2);
        s2a += __shfl_xor_sync(~0u, s2a, 1); s2a += __shfl_xor_sync(~0u, s2a, 2);
        sda += __shfl_xor_sync(~0u, sda, 1); sda += __shfl_xor_sync(~0u, sda, 2);
        s1b += __shfl_xor_sync(~0u, s1b, 1); s1b += __shfl_xor_sync(~0u, s1b, 2);
        s2b += __shfl_xor_sync(~0u, s2b, 1); s2b += __shfl_xor_sync(~0u, s2b, 2);
        sdb += __shfl_xor_sync(~0u, sdb, 1); sdb += __shfl_xor_sync(~0u, sdb, 2);
        float sca = sqrtf(s1a) / (sqrtf(s2a) + 1e-8f);
        float scb = sqrtf(s1b) / (sqrtf(s2b) + 1e-8f);
        float denA = 0.125f / (sca * sda + 1e-6f);
        float denB = 0.125f / (scb * sdb + 1e-6f);

        // phi -> A fragments entirely in registers
        uint32_t ph[8][4], pl[8][4];
#pragma unroll
        for (int kt = 0; kt < 8; kt++) {
#pragma unroll
            for (int half = 0; half < 2; half++) {
                int f = 2 * kt + half;
                float v0 = xs[f][0] * sca, v1 = xs[f][1] * sca;
                float v2 = xs[f][2] * scb, v3 = xs[f][3] * scb;
                bf16 h0 = __float2bfloat16(v0), h1 = __float2bfloat16(v1);
                bf16 h2 = __float2bfloat16(v2), h3 = __float2bfloat16(v3);
                ph[kt][half * 2] = bf2pack(h0, h1);       // row rA
                ph[kt][half * 2 + 1] = bf2pack(h2, h3);   // row rB
                pl[kt][half * 2] = bf2pack(__float2bfloat16(v0 - __bfloat162float(h0)),
                                           __float2bfloat16(v1 - __bfloat162float(h1)));
                pl[kt][half * 2 + 1] = bf2pack(__float2bfloat16(v2 - __bfloat162float(h2)),
                                               __float2bfloat16(v3 - __bfloat162float(h3)));
            }
        }

        __syncthreads();   // all warps done reading pB(h); (h=7: also done with pA/q)
        if (h < 7) copy_img_async(pB, g_wimg + (size_t)(h + 1) * IMG2);
        else       copy_img_async(pB, g_WcombImg);        // comb prefetch in gemm2 slot
        CP_COMMIT();
        CP_WAIT1();        // pC(h) done (pB prefetch may be pending)
        __syncthreads();   // pC visible to all warps

        // numerator GEMM: phi (regs) @ ktv
        ZERO16x4(acc);
        wgemm_regA(acc, ph, pl, pC);
#pragma unroll
        for (int f = 0; f < 16; f++) {
            outacc[f][0] += acc[f][0] * denA;
            outacc[f][1] += acc[f][1] * denA;
            outacc[f][2] += acc[f][2] * denB;
            outacc[f][3] += acc[f][3] * denB;
        }
        __syncthreads();   // all warps done reading pC(h)
        if (h < 7) copy_img_async(pC, g_ktvImg + (size_t)(h + 1) * IMG2);
        else       copy_img_async(pA, g_simg + (size_t)t * IMG2);   // src prefetch
        CP_COMMIT();
    }

    // comb (vss branch) — pA(src) + pB(Wcomb) already prefetched
    CP_WAIT0();
    __syncthreads();
    {
        float acc[16][4];
        ZERO16x4(acc);
        wgemm(acc, pA, pB, mrow);
#pragma unroll
        for (int f = 0; f < 16; f++) {
            int c = ((f >> 1) << 4) + ((f & 1) << 3) + ((lane & 3) << 1);
            outacc[f][0] += acc[f][0] + sBc[c];
            outacc[f][1] += acc[f][1] + sBc[c + 1];
            outacc[f][2] += acc[f][2] + sBc[c];
            outacc[f][3] += acc[f][3] + sBc[c + 1];
        }
    }

    // time coordinate + store
    float ssa = 0.f, ssb = 0.f;
#pragma unroll
    for (int f = 0; f < 16; f++) {
        ssa += outacc[f][0] * outacc[f][0] + outacc[f][1] * outacc[f][1];
        ssb += outacc[f][2] * outacc[f][2] + outacc[f][3] * outacc[f][3];
    }
    ssa += __shfl_xor_sync(~0u, ssa, 1); ssa += __shfl_xor_sync(~0u, ssa, 2);
    ssb += __shfl_xor_sync(~0u, ssb, 1); ssb += __shfl_xor_sync(~0u, ssb, 2);
    float* rowA = out + (size_t)(n0 + grA) * 129;
    float* rowB = out + (size_t)(n0 + grB) * 129;
    if ((lane & 3) == 0) {
        rowA[0] = sqrtf(ssa + 1.0f);
        rowB[0] = sqrtf(ssb + 1.0f);
    }
#pragma unroll
    for (int f = 0; f < 16; f++) {
        int c = ((f >> 1) << 4) + ((f & 1) << 3) + ((lane & 3) << 1);
        rowA[1 + c] = outacc[f][0];
        rowA[2 + c] = outacc[f][1];
        rowB[1 + c] = outacc[f][2];
        rowB[2 + c] = outacc[f][3];
    }
}

// ---------------- launch ----------------
extern "C" void kernel_launch(void* const* d_in, const int* in_sizes, int n_in,
                              void* d_out, int out_size) {
    const float* q     = (const float*)d_in[0];
    const float* src   = (const float*)d_in[1];
    const float* Wq    = (const float*)d_in[2];
    const float* Wqb   = (const float*)d_in[3];
    const float* Wk    = (const float*)d_in[4];
    const float* Wkb   = (const float*)d_in[5];
    const float* Wv    = (const float*)d_in[6];
    const float* Wvb   = (const float*)d_in[7];
    const float* vmap  = (const float*)d_in[8];
    const float* vmapb = (const float*)d_in[9];
    const float* ns    = (const float*)d_in[10];
    float* out = (float*)d_out;

    size_t sm2 = (size_t)3 * IMG2 + 512;           // ~209.4 KB
    size_t smc = (size_t)2 * IMG2 + 1024;          // ~140.3 KB
    size_t smq = (size_t)3 * IMG2 + 1536;          // ~210.4 KB
    size_t smw = (size_t)128 * PITCHF * 4;         // 67,584 B
    cudaFuncSetAttribute(k2_kv,    cudaFuncAttributeMaxDynamicSharedMemorySize, (int)sm2);
    cudaFuncSetAttribute(k2c_ktv,  cudaFuncAttributeMaxDynamicSharedMemorySize, (int)smc);
    cudaFuncSetAttribute(kq_fused, cudaFuncAttributeMaxDynamicSharedMemorySize, (int)smq);
    cudaFuncSetAttribute(kw_comb,  cudaFuncAttributeMaxDynamicSharedMemorySize, (int)smw);

    kprep<<<2 * NT + 24, 256>>>(q, src, Wq, Wk, Wv);
    kw_comb<<<16, 256, smw>>>(Wv, Wvb, vmap, vmapb);
    k2_kv<<<dim3(NC, H), 256, sm2>>>(Wkb, ns);
    k2b_reduce<<<(H * C * C) / 256, 256>>>();
    k2c_ktv<<<H, 256, smc>>>(Wvb);
    kq_fused<<<NT, 256, smq>>>(Wqb, ns, out);
}

// round 15
// speedup vs baseline: 1.2989x; 1.1901x over previous
#include <cuda_runtime.h>
#include <cuda_fp16.h>
#include <math.h>
#include <stdint.h>

#define NROWS 32768
#define C 128
#define H 8
#define NC 64
#define SUBT 4
#define NT (NROWS / 128)
#define KP 136                 // plane row pitch in fp16 elems (272B)
#define PLANEB 34816           // bytes per 128-row plane
#define PLANEE 17408           // elems per plane
#define IMG2 69632             // hi+lo image bytes
#define PITCHF 132

typedef __half f16;

// ---------------- scratch ----------------
__device__ float    g_M_part[NC * H * C * C];        // [c][h][m][i] fp32 partials of phi^T src
__device__ float    g_kss_part[NC * H * C];
__device__ char     g_Mimg[(size_t)H * IMG2];        // M[h] split images (row m, col i)
__device__ char     g_ktvImg[(size_t)H * IMG2];      // KtV[h] split images (row d, col m)
__device__ float    g_kss[H * C];
__device__ char     g_WcombImg[IMG2];                // Wcomb split image (row o, col i)
__device__ float    g_bcomb[C];
__device__ char     g_qimg[(size_t)NT * IMG2];
__device__ char     g_simg[(size_t)NT * IMG2];
__device__ char     g_wimg[(size_t)24 * IMG2];       // Wq[8],Wk[8],Wv[8]

// ---------------- low-level ----------------
__device__ __forceinline__ uint32_t smem_u32(const void* p) {
    return (uint32_t)__cvta_generic_to_shared(p);
}
__device__ __forceinline__ void ldm4(uint32_t r[4], const f16* p) {
    uint32_t a = smem_u32(p);
    asm volatile("ldmatrix.sync.aligned.m8n8.x4.shared.b16 {%0,%1,%2,%3}, [%4];"
                 : "=r"(r[0]), "=r"(r[1]), "=r"(r[2]), "=r"(r[3]) : "r"(a));
}
__device__ __forceinline__ void ldm4t(uint32_t r[4], const f16* p) {
    uint32_t a = smem_u32(p);
    asm volatile("ldmatrix.sync.aligned.m8n8.x4.trans.shared.b16 {%0,%1,%2,%3}, [%4];"
                 : "=r"(r[0]), "=r"(r[1]), "=r"(r[2]), "=r"(r[3]) : "r"(a));
}
__device__ __forceinline__ void mma_f16(float d[4], const uint32_t a[4],
                                        uint32_t b0, uint32_t b1) {
    asm volatile(
        "mma.sync.aligned.m16n8k16.row.col.f32.f16.f16.f32 "
        "{%0,%1,%2,%3},{%4,%5,%6,%7},{%8,%9},{%0,%1,%2,%3};"
        : "+f"(d[0]), "+f"(d[1]), "+f"(d[2]), "+f"(d[3])
        : "r"(a[0]), "r"(a[1]), "r"(a[2]), "r"(a[3]), "r"(b0), "r"(b1));
}
__device__ __forceinline__ uint32_t h2pack(f16 x, f16 y) {
    return (uint32_t)__half_as_ushort(x) | ((uint32_t)__half_as_ushort(y) << 16);
}
__device__ __forceinline__ void cpa16(uint32_t d, const void* s) {
    asm volatile("cp.async.cg.shared.global [%0], [%1], 16;" ::"r"(d), "l"(s));
}
#define CP_COMMIT() asm volatile("cp.async.commit_group;" ::: "memory")
#define CP_WAIT0()  asm volatile("cp.async.wait_group 0;" ::: "memory")
#define CP_WAIT1()  asm volatile("cp.async.wait_group 1;" ::: "memory")

// 256-thread async 68KB image copy
__device__ __forceinline__ void copy_img_async(char* dst, const char* __restrict__ src) {
    uint32_t d = smem_u32(dst);
    int tid = threadIdx.x;
#pragma unroll
    for (int it = 0; it < 17; it++) {
        int i = (tid + it * 256) * 16;
        cpa16(d + i, src + i);
    }
}

// fp16 split store into hi+lo planes (plane row m, col r); works gmem/smem
__device__ __forceinline__ void storeT_p(char* p, int m, int r, float x) {
    f16 h = __float2half_rn(x);
    int ob = m * 272 + r * 2;
    *(f16*)(p + ob) = h;
    *(f16*)(p + PLANEB + ob) = __float2half_rn(x - __half2float(h));
}
// hi-plane-only store (for phi^T; lo never consumed)
__device__ __forceinline__ void storeT_hi(char* p, int m, int r, float x) {
    *(f16*)(p + m * 272 + r * 2) = __float2half_rn(x);
}

// 3-pass split warp GEMM: rows [mrow,mrow+16) x 128 cols, K=128
__device__ __forceinline__ void wgemm(float acc[16][4], const char* pA, const char* pB,
                                      int mrow) {
    const f16* Ahi = (const f16*)pA;
    const f16* Alo = Ahi + PLANEE;
    const f16* Bhi = (const f16*)pB;
    const f16* Blo = Bhi + PLANEE;
    int lane = threadIdx.x & 31;
    int lr = lane & 15, lc = lane >> 4;
#pragma unroll
    for (int kt = 0; kt < 8; kt++) {
        int aoff = (mrow + lr) * KP + kt * 16 + lc * 8;
        uint32_t ah[4], al[4];
        ldm4(ah, Ahi + aoff);
        ldm4(al, Alo + aoff);
#pragma unroll
        for (int nt = 0; nt < 8; nt++) {
            int boff = (nt * 16 + lr) * KP + kt * 16 + lc * 8;
            uint32_t bh[4], bl[4];
            ldm4(bh, Bhi + boff);
            ldm4(bl, Blo + boff);
            mma_f16(acc[nt * 2], ah, bh[0], bh[2]);
            mma_f16(acc[nt * 2], ah, bl[0], bl[2]);
            mma_f16(acc[nt * 2], al, bh[0], bh[2]);
            mma_f16(acc[nt * 2 + 1], ah, bh[1], bh[3]);
            mma_f16(acc[nt * 2 + 1], ah, bl[1], bl[3]);
            mma_f16(acc[nt * 2 + 1], al, bh[1], bh[3]);
        }
    }
}

// 2-pass warp GEMM (A hi only): acc += Ah*Bh + Ah*Bl
__device__ __forceinline__ void wgemm2(float acc[16][4], const char* pA, const char* pB,
                                       int mrow) {
    const f16* Ahi = (const f16*)pA;
    const f16* Bhi = (const f16*)pB;
    const f16* Blo = Bhi + PLANEE;
    int lane = threadIdx.x & 31;
    int lr = lane & 15, lc = lane >> 4;
#pragma unroll
    for (int kt = 0; kt < 8; kt++) {
        int aoff = (mrow + lr) * KP + kt * 16 + lc * 8;
        uint32_t ah[4];
        ldm4(ah, Ahi + aoff);
#pragma unroll
        for (int nt = 0; nt < 8; nt++) {
            int boff = (nt * 16 + lr) * KP + kt * 16 + lc * 8;
            uint32_t bh[4], bl[4];
            ldm4(bh, Bhi + boff);
            ldm4(bl, Blo + boff);
            mma_f16(acc[nt * 2], ah, bh[0], bh[2]);
            mma_f16(acc[nt * 2], ah, bl[0], bl[2]);
            mma_f16(acc[nt * 2 + 1], ah, bh[1], bh[3]);
            mma_f16(acc[nt * 2 + 1], ah, bl[1], bl[3]);
        }
    }
}

// 2-pass GEMM with A fragments in registers: acc += phA*Bh + phA*Bl
__device__ __forceinline__ void wgemm_regA(float acc[16][4], const uint32_t ph[8][4],
                                           const char* pB) {
    const f16* Bhi = (const f16*)pB;
    const f16* Blo = Bhi + PLANEE;
    int lane = threadIdx.x & 31;
    int lr = lane & 15, lc = lane >> 4;
#pragma unroll
    for (int kt = 0; kt < 8; kt++) {
#pragma unroll
        for (int nt = 0; nt < 8; nt++) {
            int boff = (nt * 16 + lr) * KP + kt * 16 + lc * 8;
            uint32_t bh[4], bl[4];
            ldm4(bh, Bhi + boff);
            ldm4(bl, Blo + boff);
            mma_f16(acc[nt * 2], ph[kt], bh[0], bh[2]);
            mma_f16(acc[nt * 2], ph[kt], bl[0], bl[2]);
            mma_f16(acc[nt * 2 + 1], ph[kt], bh[1], bh[3]);
            mma_f16(acc[nt * 2 + 1], ph[kt], bl[1], bl[3]);
        }
    }
}

// 2-pass trans-B warp GEMM (A hi only): acc[m][i] += Ah[m][r] * (Sh+Sl)[r][i]
__device__ __forceinline__ void wgemm_trans(float acc[16][4], const char* pA, const char* pS,
                                            int mrow) {
    const f16* Ahi = (const f16*)pA;
    const f16* Shi = (const f16*)pS;
    const f16* Slo = Shi + PLANEE;
    int lane = threadIdx.x & 31;
    int lr = lane & 15, lc = lane >> 4;
#pragma unroll
    for (int kt = 0; kt < 8; kt++) {
        int aoff = (mrow + lr) * KP + kt * 16 + lc * 8;
        uint32_t ah[4];
        ldm4(ah, Ahi + aoff);
#pragma unroll
        for (int nt = 0; nt < 8; nt++) {
            int boff = (kt * 16 + lr) * KP + nt * 16 + lc * 8;
            uint32_t bh[4], bl[4];
            ldm4t(bh, Shi + boff);
            ldm4t(bl, Slo + boff);
            mma_f16(acc[nt * 2], ah, bh[0], bh[1]);
            mma_f16(acc[nt * 2], ah, bl[0], bl[1]);
            mma_f16(acc[nt * 2 + 1], ah, bh[2], bh[3]);
            mma_f16(acc[nt * 2 + 1], ah, bl[2], bl[3]);
        }
    }
}

#define ZERO16x4(a)                                   \
    _Pragma("unroll") for (int _f = 0; _f < 16; _f++) \
        { a[_f][0] = 0.f; a[_f][1] = 0.f; a[_f][2] = 0.f; a[_f][3] = 0.f; }

// ---------------- kprep: fp32 -> split-fp16 images ----------------
__global__ void __launch_bounds__(256, 1)
kprep(const float* __restrict__ q, const float* __restrict__ src,
      const float* __restrict__ Wq, const float* __restrict__ Wk,
      const float* __restrict__ Wv) {
    int b = blockIdx.x;
    const float* g;
    char* dst;
    if (b < NT) { g = q + (size_t)b * 128 * C; dst = g_qimg + (size_t)b * IMG2; }
    else if (b < 2 * NT) { g = src + (size_t)(b - NT) * 128 * C; dst = g_simg + (size_t)(b - NT) * IMG2; }
    else {
        int i = b - 2 * NT;
        int mat = i >> 3, h = i & 7;
        g = ((mat == 0) ? Wq : (mat == 1) ? Wk : Wv) + (size_t)h * C * C;
        dst = g_wimg + (size_t)i * IMG2;
    }
    char* lo = dst + PLANEB;
    int tid = threadIdx.x;
#pragma unroll
    for (int it = 0; it < 8; it++) {
        int idx = tid + it * 256;
        int row = idx >> 4, c0 = (idx & 15) << 3;
        float4 a = *(const float4*)(g + (size_t)row * C + c0);
        float4 bb = *(const float4*)(g + (size_t)row * C + c0 + 4);
        float v8[8] = {a.x, a.y, a.z, a.w, bb.x, bb.y, bb.z, bb.w};
        uint32_t hw[4], lw[4];
#pragma unroll
        for (int i2 = 0; i2 < 4; i2++) {
            f16 h0 = __float2half_rn(v8[2 * i2]);
            f16 h1 = __float2half_rn(v8[2 * i2 + 1]);
            f16 l0 = __float2half_rn(v8[2 * i2] - __half2float(h0));
            f16 l1 = __float2half_rn(v8[2 * i2 + 1] - __half2float(h1));
            hw[i2] = h2pack(h0, h1);
            lw[i2] = h2pack(l0, l1);
        }
        int ob = row * 272 + c0 * 2;
        *(uint4*)(dst + ob) = make_uint4(hw[0], hw[1], hw[2], hw[3]);
        *(uint4*)(lo + ob) = make_uint4(lw[0], lw[1], lw[2], lw[3]);
    }
}

// ---------------- kw_comb: combined vss weights -> split image ----------------
__global__ void __launch_bounds__(256, 1)
kw_comb(const float* __restrict__ Wv, const float* __restrict__ Wvb,
        const float* __restrict__ vmap, const float* __restrict__ vmapb) {
    extern __shared__ char smraw[];
    float* sWb = (float*)smraw;
    int tid = threadIdx.x, lane = tid & 31, w = tid >> 5;
#pragma unroll
    for (int it = 0; it < 64; it++) {
        int idx = tid + it * 256;
        int d = idx >> 7, i = idx & 127;
        float s = 0.f;
#pragma unroll
        for (int h = 0; h < H; h++) s += Wv[((size_t)h * C + d) * C + i];
        sWb[d * PITCHF + i] = s * 0.125f;
    }
    __syncthreads();
    int o = blockIdx.x * 8 + w;
    float r[4] = {0.f, 0.f, 0.f, 0.f};
    for (int d = 0; d < 128; d++) {
        float vm = vmap[(size_t)o * C + d];
#pragma unroll
        for (int k = 0; k < 4; k++) r[k] += vm * sWb[d * PITCHF + lane + 32 * k];
    }
#pragma unroll
    for (int k = 0; k < 4; k++) storeT_p(g_WcombImg, o, lane + 32 * k, r[k]);
    if (blockIdx.x == 0 && tid < 128) {
        float s = 0.f;
        for (int d = 0; d < 128; d++) {
            float bv = 0.f;
#pragma unroll
            for (int h = 0; h < H; h++) bv += Wvb[h * C + d];
            s += vmap[(size_t)tid * C + d] * (bv * 0.125f);
        }
        g_bcomb[tid] = s + vmapb[tid];
    }
}

// ---------------- K2: per (chunk, head): phi_k -> M += phi^T src, kss ----------------
#define K2_BIA (3 * IMG2)
__global__ void __launch_bounds__(256, 1)
k2_kv(const float* __restrict__ Wkb, const float* __restrict__ ns) {
    extern __shared__ char sm[];
    char* pA = sm;               // src image
    char* pB = sm + IMG2;        // Wk (static all subtiles)
    char* pP = sm + 2 * IMG2;    // phi^T (hi plane only used)
    float* sBk = (float*)(sm + K2_BIA);
    int chunk = blockIdx.x, h = blockIdx.y;
    int tid = threadIdx.x, w = tid >> 5, lane = tid & 31;
    int mrow = w * 16;
    int grA = mrow + (lane >> 2), grB = grA + 8;
    float ids = 1.f / (fabsf(ns[0]) + 1e-6f);

    if (tid < 128) sBk[tid] = Wkb[h * C + tid];
    float accM[16][4];
    ZERO16x4(accM);
    float kss_loc = 0.f;

    copy_img_async(pB, g_wimg + (size_t)(8 + h) * IMG2);
    copy_img_async(pA, g_simg + (size_t)(chunk * SUBT) * IMG2);
    CP_COMMIT();

    for (int s = 0; s < SUBT; s++) {
        if (s > 0) {
            __syncthreads();
            copy_img_async(pA, g_simg + (size_t)(chunk * SUBT + s) * IMG2);
            CP_COMMIT();
        }
        CP_WAIT0();
        __syncthreads();

        float acc[16][4];
        ZERO16x4(acc);
        wgemm(acc, pA, pB, mrow);          // 3-pass, accuracy-critical

        float xs[16][4], s1a = 0.f, s2a = 0.f, s1b = 0.f, s2b = 0.f;
#pragma unroll
        for (int f = 0; f < 16; f++) {
            int c = ((f >> 1) << 4) + ((f & 1) << 3) + ((lane & 3) << 1);
            float b0 = sBk[c], b1 = sBk[c + 1];
            float x;
            x = (fmaxf(acc[f][0] + b0, 0.f) + 1e-6f) * ids; x *= x; xs[f][0] = x; s1a += x; s2a += x * x;
            x = (fmaxf(acc[f][1] + b1, 0.f) + 1e-6f) * ids; x *= x; xs[f][1] = x; s1a += x; s2a += x * x;
            x = (fmaxf(acc[f][2] + b0, 0.f) + 1e-6f) * ids; x *= x; xs[f][2] = x; s1b += x; s2b += x * x;
            x = (fmaxf(acc[f][3] + b1, 0.f) + 1e-6f) * ids; x *= x; xs[f][3] = x; s1b += x; s2b += x * x;
        }
        s1a += __shfl_xor_sync(~0u, s1a, 1); s1a += __shfl_xor_sync(~0u, s1a, 2);
        s2a += __shfl_xor_sync(~0u, s2a, 1); s2a += __shfl_xor_sync(~0u, s2a, 2);
        s1b += __shfl_xor_sync(~0u, s1b, 1); s1b += __shfl_xor_sync(~0u, s1b, 2);
        s2b += __shfl_xor_sync(~0u, s2b, 1); s2b += __shfl_xor_sync(~0u, s2b, 2);
        float sca = sqrtf(s1a) / (sqrtf(s2a) + 1e-8f);
        float scb = sqrtf(s1b) / (sqrtf(s2b) + 1e-8f);
#pragma unroll
        for (int f = 0; f < 16; f++) {
            int c = ((f >> 1) << 4) + ((f & 1) << 3) + ((lane & 3) << 1);
            storeT_hi(pP, c, grA, xs[f][0] * sca);
            storeT_hi(pP, c + 1, grA, xs[f][1] * sca);
            storeT_hi(pP, c, grB, xs[f][2] * scb);
            storeT_hi(pP, c + 1, grB, xs[f][3] * scb);
        }
        __syncthreads();   // phi^T hi fully visible

        if (tid < 128) {
            float s0 = 0.f;
#pragma unroll 8
            for (int r = 0; r < 128; r++)
                s0 += __half2float(*(f16*)(pP + tid * 272 + r * 2));
            kss_loc += s0;
        }
        wgemm_trans(accM, pP, pA, mrow);   // 2-pass (A hi only)
    }

    size_t base = ((size_t)(chunk * H + h)) * C * C;
#pragma unroll
    for (int f = 0; f < 16; f++) {
        int c = ((f >> 1) << 4) + ((f & 1) << 3) + ((lane & 3) << 1);
        *(float2*)(g_M_part + base + (size_t)grA * C + c) = make_float2(accM[f][0], accM[f][1]);
        *(float2*)(g_M_part + base + (size_t)grB * C + c) = make_float2(accM[f][2], accM[f][3]);
    }
    if (tid < 128)
        g_kss_part[(size_t)(chunk * H + h) * C + tid] = kss_loc;
}

// ---------------- K2b: reduce M parts -> split image; reduce kss ----------------
__global__ void k2b_reduce() {
    int i = blockIdx.x * blockDim.x + threadIdx.x;
    int h = i >> 14, rem = i & 16383, m = rem >> 7, ii = rem & 127;
    float s = 0.f;
#pragma unroll 8
    for (int c = 0; c < NC; c++) s += g_M_part[(size_t)c * (H * C * C) + i];
    storeT_p(g_Mimg + (size_t)h * IMG2, m, ii, s);
    if (i < H * C) {
        float s2 = 0.f;
#pragma unroll 8
        for (int c = 0; c < NC; c++) s2 += g_kss_part[(size_t)c * (H * C) + i];
        g_kss[i] = s2;
    }
}

// ---------------- K2c: KtV[h] = M[h] @ Wv[h]^T + kss⊗b -> split image [d][m] ----------------
__global__ void __launch_bounds__(256, 1)
k2c_ktv(const float* __restrict__ Wvb) {
    extern __shared__ char sm[];
    char* pA = sm;
    char* pB = sm + IMG2;
    float* sKss = (float*)(sm + 2 * IMG2);
    float* sBv = sKss + 128;
    int h = blockIdx.x;
    int tid = threadIdx.x, w = tid >> 5, lane = tid & 31;
    int mrow = w * 16;
    int grA = mrow + (lane >> 2), grB = grA + 8;

    copy_img_async(pA, g_Mimg + (size_t)h * IMG2);
    copy_img_async(pB, g_wimg + (size_t)(16 + h) * IMG2);
    CP_COMMIT();
    if (tid < 128) {
        sKss[tid] = g_kss[h * C + tid];
        sBv[tid] = Wvb[h * C + tid];
    }
    CP_WAIT0();
    __syncthreads();

    float acc[16][4];
    ZERO16x4(acc);
    wgemm(acc, pA, pB, mrow);   // 3-pass (tiny kernel, keep accuracy)
    float kssA = sKss[grA], kssB = sKss[grB];
    char* img = g_ktvImg + (size_t)h * IMG2;
#pragma unroll
    for (int f = 0; f < 16; f++) {
        int c = ((f >> 1) << 4) + ((f & 1) << 3) + ((lane & 3) << 1);
        storeT_p(img, c, grA, acc[f][0] + kssA * sBv[c]);
        storeT_p(img, c + 1, grA, acc[f][1] + kssA * sBv[c + 1]);
        storeT_p(img, c, grB, acc[f][2] + kssB * sBv[c]);
        storeT_p(img, c + 1, grB, acc[f][3] + kssB * sBv[c + 1]);
    }
}

// ---------------- KQ: fused phi_q + numerator + comb + epilogue ----------------
#define KQ_MISC (3 * IMG2)
__global__ void __launch_bounds__(256, 1)
kq_fused(const float* __restrict__ Wqb, const float* __restrict__ ns,
         float* __restrict__ out) {
    extern __shared__ char sm[];
    char* pA = sm;               // q image (persistent), then src
    char* pB = sm + IMG2;        // Wq[h] (prefetched), then Wcomb
    char* pC = sm + 2 * IMG2;    // ktv image (prefetched)
    float* sBias = (float*)(sm + KQ_MISC);
    float* sKs = sBias + 128;
    float* sBc = sKs + 128;
    int t = blockIdx.x, n0 = t * 128;
    int tid = threadIdx.x, w = tid >> 5, lane = tid & 31;
    int mrow = w * 16;
    int grA = mrow + (lane >> 2), grB = grA + 8;
    float ids = 1.f / (fabsf(ns[0]) + 1e-6f);

    // group 1: pA + pB(0); group 2: pC(0)
    copy_img_async(pA, g_qimg + (size_t)t * IMG2);
    copy_img_async(pB, g_wimg);
    CP_COMMIT();
    copy_img_async(pC, g_ktvImg);
    CP_COMMIT();
    if (tid < 128) sBc[tid] = g_bcomb[tid];

    float outacc[16][4];
    ZERO16x4(outacc);

    for (int h = 0; h < H; h++) {
        CP_WAIT1();        // pA + pB(h) ready (pC(h) may still be in flight)
        if (tid < 128) {
            sBias[tid] = Wqb[h * C + tid];
            sKs[tid] = g_kss[h * C + tid];
        }
        __syncthreads();

        float acc[16][4];
        ZERO16x4(acc);
        wgemm(acc, pA, pB, mrow);          // 3-pass

        float xs[16][4];
        float s1a = 0.f, s2a = 0.f, sda = 0.f, s1b = 0.f, s2b = 0.f, sdb = 0.f;
#pragma unroll
        for (int f = 0; f < 16; f++) {
            int c = ((f >> 1) << 4) + ((f & 1) << 3) + ((lane & 3) << 1);
            float b0 = sBias[c], b1 = sBias[c + 1];
            float k0 = sKs[c], k1 = sKs[c + 1];
            float x;
            x = (fmaxf(acc[f][0] + b0, 0.f) + 1e-6f) * ids; x *= x; xs[f][0] = x; s1a += x; s2a += x * x; sda += x * k0;
            x = (fmaxf(acc[f][1] + b1, 0.f) + 1e-6f) * ids; x *= x; xs[f][1] = x; s1a += x; s2a += x * x; sda += x * k1;
            x = (fmaxf(acc[f][2] + b0, 0.f) + 1e-6f) * ids; x *= x; xs[f][2] = x; s1b += x; s2b += x * x; sdb += x * k0;
            x = (fmaxf(acc[f][3] + b1, 0.f) + 1e-6f) * ids; x *= x; xs[f][3] = x; s1b += x; s2b += x * x; sdb += x * k1;
        }
        s1a += __shfl_xor_sync(~0u, s1a, 1); s1a += __shfl_xor_sync(~0u, s1a, 2);
        s2a += __shfl_xor_sync(~0u, s2a, 1); s2a += __shfl_xor_sync(~0u, s2a, 2);
        sda += __shfl_xor_sync(~0u, sda, 1); sda += __shfl_xor_sync(~0u, sda, 2);
        s1b += __shfl_xor_sync(~0u, s1b, 1); s1b += __shfl_xor_sync(~0u, s1b, 2);
        s2b += __shfl_xor_sync(~0u, s2b, 1); s2b += __shfl_xor_sync(~0u, s2b, 2);
        sdb += __shfl_xor_sync(~0u, sdb, 1); sdb += __shfl_xor_sync(~0u, sdb, 2);
        float sca = sqrtf(s1a) / (sqrtf(s2a) + 1e-8f);
        float scb = sqrtf(s1b) / (sqrtf(s2b) + 1e-8f);
        float denA = 0.125f / (sca * sda + 1e-6f);
        float denB = 0.125f / (scb * sdb + 1e-6f);

        // phi -> hi A-fragments in registers (lo dropped; 2-pass gemm2)
        uint32_t ph[8][4];
#pragma unroll
        for (int kt = 0; kt < 8; kt++) {
#pragma unroll
            for (int half = 0; half < 2; half++) {
                int f = 2 * kt + half;
                ph[kt][half * 2] = h2pack(__float2half_rn(xs[f][0] * sca),
                                          __float2half_rn(xs[f][1] * sca));
                ph[kt][half * 2 + 1] = h2pack(__float2half_rn(xs[f][2] * scb),
                                              __float2half_rn(xs[f][3] * scb));
            }
        }

        __syncthreads();   // all warps done reading pB(h)
        int hn = (h < 7) ? h + 1 : 7;
        copy_img_async(pB, g_wimg + (size_t)hn * IMG2);   // overlaps gemm2
        CP_COMMIT();
        CP_WAIT1();        // pC(h) done (pB prefetch may be pending)
        __syncthreads();   // pC visible to all warps

        // numerator GEMM: phi (regs, 2-pass) @ ktv
        ZERO16x4(acc);
        wgemm_regA(acc, ph, pC);
#pragma unroll
        for (int f = 0; f < 16; f++) {
            outacc[f][0] += acc[f][0] * denA;
            outacc[f][1] += acc[f][1] * denA;
            outacc[f][2] += acc[f][2] * denB;
            outacc[f][3] += acc[f][3] * denB;
        }
        __syncthreads();   // all warps done reading pC(h)
        if (h < 7) copy_img_async(pC, g_ktvImg + (size_t)(h + 1) * IMG2);
        else       copy_img_async(pA, g_simg + (size_t)t * IMG2);   // src prefetch
        CP_COMMIT();
    }

    // comb (vss branch)
    CP_WAIT0();            // drain stray prefetches
    __syncthreads();
    copy_img_async(pB, g_WcombImg);
    CP_COMMIT();
    CP_WAIT0();
    __syncthreads();
    {
        float acc[16][4];
        ZERO16x4(acc);
        wgemm2(acc, pA, pB, mrow);         // 2-pass
#pragma unroll
        for (int f = 0; f < 16; f++) {
            int c = ((f >> 1) << 4) + ((f & 1) << 3) + ((lane & 3) << 1);
            outacc[f][0] += acc[f][0] + sBc[c];
            outacc[f][1] += acc[f][1] + sBc[c + 1];
            outacc[f][2] += acc[f][2] + sBc[c];
            outacc[f][3] += acc[f][3] + sBc[c + 1];
        }
    }

    // time coordinate + store
    float ssa = 0.f, ssb = 0.f;
#pragma unroll
    for (int f = 0; f < 16; f++) {
        ssa += outacc[f][0] * outacc[f][0] + outacc[f][1] * outacc[f][1];
        ssb += outacc[f][2] * outacc[f][2] + outacc[f][3] * outacc[f][3];
    }
    ssa += __shfl_xor_sync(~0u, ssa, 1); ssa += __shfl_xor_sync(~0u, ssa, 2);
    ssb += __shfl_xor_sync(~0u, ssb, 1); ssb += __shfl_xor_sync(~0u, ssb, 2);
    float* rowA = out + (size_t)(n0 + grA) * 129;
    float* rowB = out + (size_t)(n0 + grB) * 129;
    if ((lane & 3) == 0) {
        rowA[0] = sqrtf(ssa + 1.0f);
        rowB[0] = sqrtf(ssb + 1.0f);
    }
#pragma unroll
    for (int f = 0; f < 16; f++) {
        int c = ((f >> 1) << 4) + ((f & 1) << 3) + ((lane & 3) << 1);
        rowA[1 + c] = outacc[f][0];
        rowA[2 + c] = outacc[f][1];
        rowB[1 + c] = outacc[f][2];
        rowB[2 + c] = outacc[f][3];
    }
}

// ---------------- launch ----------------
extern "C" void kernel_launch(void* const* d_in, const int* in_sizes, int n_in,
                              void* d_out, int out_size) {
    const float* q     = (const float*)d_in[0];
    const float* src   = (const float*)d_in[1];
    const float* Wq    = (const float*)d_in[2];
    const float* Wqb   = (const float*)d_in[3];
    const float* Wk    = (const float*)d_in[4];
    const float* Wkb   = (const float*)d_in[5];
    const float* Wv    = (const float*)d_in[6];
    const float* Wvb   = (const float*)d_in[7];
    const float* vmap  = (const float*)d_in[8];
    const float* vmapb = (const float*)d_in[9];
    const float* ns    = (const float*)d_in[10];
    float* out = (float*)d_out;

    size_t sm2 = (size_t)3 * IMG2 + 512;           // ~209.4 KB
    size_t smc = (size_t)2 * IMG2 + 1024;          // ~140.3 KB
    size_t smq = (size_t)3 * IMG2 + 1536;          // ~210.4 KB
    size_t smw = (size_t)128 * PITCHF * 4;         // 67,584 B
    cudaFuncSetAttribute(k2_kv,    cudaFuncAttributeMaxDynamicSharedMemorySize, (int)sm2);
    cudaFuncSetAttribute(k2c_ktv,  cudaFuncAttributeMaxDynamicSharedMemorySize, (int)smc);
    cudaFuncSetAttribute(kq_fused, cudaFuncAttributeMaxDynamicSharedMemorySize, (int)smq);
    cudaFuncSetAttribute(kw_comb,  cudaFuncAttributeMaxDynamicSharedMemorySize, (int)smw);

    kprep<<<2 * NT + 24, 256>>>(q, src, Wq, Wk, Wv);
    kw_comb<<<16, 256, smw>>>(Wv, Wvb, vmap, vmapb);
    k2_kv<<<dim3(NC, H), 256, sm2>>>(Wkb, ns);
    k2b_reduce<<<(H * C * C) / 256, 256>>>();
    k2c_ktv<<<H, 256, smc>>>(Wvb);
    kq_fused<<<NT, 256, smq>>>(Wqb, ns, out);
}

// round 16
// speedup vs baseline: 1.4141x; 1.0887x over previous
#include <cuda_runtime.h>
#include <cuda_fp16.h>
#include <math.h>
#include <stdint.h>

#define NROWS 32768
#define C 128
#define H 8
#define NC 64
#define SUBT 4
#define NT (NROWS / 128)
#define KP 136                 // plane row pitch in fp16 elems (272B)
#define PLANEB 34816           // bytes per 128-row plane
#define PLANEE 17408           // elems per plane
#define IMG2 69632             // hi+lo image bytes
#define PITCHF 132

typedef __half f16;

// ---------------- scratch ----------------
__device__ float    g_M_part[NC * H * C * C];        // [c][h][m][i] fp32 partials of phi^T src
__device__ float    g_kss_part[NC * H * C];
__device__ char     g_Mimg[(size_t)H * IMG2];        // M[h] split images (row m, col i)
__device__ char     g_ktvImg[(size_t)H * IMG2];      // KtV[h] split images (row d, col m)
__device__ float    g_kss[H * C];
__device__ char     g_WcombImg[IMG2];                // Wcomb split image (row o, col i)
__device__ float    g_bcomb[C];
__device__ char     g_qimg[(size_t)NT * IMG2];
__device__ char     g_simg[(size_t)NT * IMG2];
__device__ char     g_wimg[(size_t)24 * IMG2];       // Wq[8],Wk[8],Wv[8]

// ---------------- low-level ----------------
__device__ __forceinline__ uint32_t smem_u32(const void* p) {
    return (uint32_t)__cvta_generic_to_shared(p);
}
__device__ __forceinline__ void ldm4(uint32_t r[4], const f16* p) {
    uint32_t a = smem_u32(p);
    asm volatile("ldmatrix.sync.aligned.m8n8.x4.shared.b16 {%0,%1,%2,%3}, [%4];"
                 : "=r"(r[0]), "=r"(r[1]), "=r"(r[2]), "=r"(r[3]) : "r"(a));
}
__device__ __forceinline__ void ldm4t(uint32_t r[4], const f16* p) {
    uint32_t a = smem_u32(p);
    asm volatile("ldmatrix.sync.aligned.m8n8.x4.trans.shared.b16 {%0,%1,%2,%3}, [%4];"
                 : "=r"(r[0]), "=r"(r[1]), "=r"(r[2]), "=r"(r[3]) : "r"(a));
}
__device__ __forceinline__ void mma_f16(float d[4], const uint32_t a[4],
                                        uint32_t b0, uint32_t b1) {
    asm volatile(
        "mma.sync.aligned.m16n8k16.row.col.f32.f16.f16.f32 "
        "{%0,%1,%2,%3},{%4,%5,%6,%7},{%8,%9},{%0,%1,%2,%3};"
        : "+f"(d[0]), "+f"(d[1]), "+f"(d[2]), "+f"(d[3])
        : "r"(a[0]), "r"(a[1]), "r"(a[2]), "r"(a[3]), "r"(b0), "r"(b1));
}
__device__ __forceinline__ uint32_t h2pack(f16 x, f16 y) {
    return (uint32_t)__half_as_ushort(x) | ((uint32_t)__half_as_ushort(y) << 16);
}
__device__ __forceinline__ void cpa16(uint32_t d, const void* s) {
    asm volatile("cp.async.cg.shared.global [%0], [%1], 16;" ::"r"(d), "l"(s));
}
#define CP_COMMIT() asm volatile("cp.async.commit_group;" ::: "memory")
#define CP_WAIT0()  asm volatile("cp.async.wait_group 0;" ::: "memory")
#define CP_WAIT1()  asm volatile("cp.async.wait_group 1;" ::: "memory")

// 256-thread async 68KB image copy
__device__ __forceinline__ void copy_img_async(char* dst, const char* __restrict__ src) {
    uint32_t d = smem_u32(dst);
    int tid = threadIdx.x;
#pragma unroll
    for (int it = 0; it < 17; it++) {
        int i = (tid + it * 256) * 16;
        cpa16(d + i, src + i);
    }
}
// hi-plane-only copy (34KB) for A-hi-only consumers
__device__ __forceinline__ void copy_plane_async(char* dst, const char* __restrict__ src) {
    uint32_t d = smem_u32(dst);
    int tid = threadIdx.x;
    for (int i = tid; i < PLANEB / 16; i += 256)
        cpa16(d + i * 16, src + i * 16);
}

// fp16 split store into hi+lo planes (plane row m, col r); works gmem/smem
__device__ __forceinline__ void storeT_p(char* p, int m, int r, float x) {
    f16 h = __float2half_rn(x);
    int ob = m * 272 + r * 2;
    *(f16*)(p + ob) = h;
    *(f16*)(p + PLANEB + ob) = __float2half_rn(x - __half2float(h));
}
// hi-plane-only store (for phi^T; lo never consumed)
__device__ __forceinline__ void storeT_hi(char* p, int m, int r, float x) {
    *(f16*)(p + m * 272 + r * 2) = __float2half_rn(x);
}

// 3-pass split warp GEMM: rows [mrow,mrow+16) x 128 cols, K=128 (k2c only)
__device__ __forceinline__ void wgemm(float acc[16][4], const char* pA, const char* pB,
                                      int mrow) {
    const f16* Ahi = (const f16*)pA;
    const f16* Alo = Ahi + PLANEE;
    const f16* Bhi = (const f16*)pB;
    const f16* Blo = Bhi + PLANEE;
    int lane = threadIdx.x & 31;
    int lr = lane & 15, lc = lane >> 4;
#pragma unroll
    for (int kt = 0; kt < 8; kt++) {
        int aoff = (mrow + lr) * KP + kt * 16 + lc * 8;
        uint32_t ah[4], al[4];
        ldm4(ah, Ahi + aoff);
        ldm4(al, Alo + aoff);
#pragma unroll
        for (int nt = 0; nt < 8; nt++) {
            int boff = (nt * 16 + lr) * KP + kt * 16 + lc * 8;
            uint32_t bh[4], bl[4];
            ldm4(bh, Bhi + boff);
            ldm4(bl, Blo + boff);
            mma_f16(acc[nt * 2], ah, bh[0], bh[2]);
            mma_f16(acc[nt * 2], ah, bl[0], bl[2]);
            mma_f16(acc[nt * 2], al, bh[0], bh[2]);
            mma_f16(acc[nt * 2 + 1], ah, bh[1], bh[3]);
            mma_f16(acc[nt * 2 + 1], ah, bl[1], bl[3]);
            mma_f16(acc[nt * 2 + 1], al, bh[1], bh[3]);
        }
    }
}

// 2-pass warp GEMM (A hi only): acc += Ah*Bh + Ah*Bl
__device__ __forceinline__ void wgemm2(float acc[16][4], const char* pA, const char* pB,
                                       int mrow) {
    const f16* Ahi = (const f16*)pA;
    const f16* Bhi = (const f16*)pB;
    const f16* Blo = Bhi + PLANEE;
    int lane = threadIdx.x & 31;
    int lr = lane & 15, lc = lane >> 4;
#pragma unroll
    for (int kt = 0; kt < 8; kt++) {
        int aoff = (mrow + lr) * KP + kt * 16 + lc * 8;
        uint32_t ah[4];
        ldm4(ah, Ahi + aoff);
#pragma unroll
        for (int nt = 0; nt < 8; nt++) {
            int boff = (nt * 16 + lr) * KP + kt * 16 + lc * 8;
            uint32_t bh[4], bl[4];
            ldm4(bh, Bhi + boff);
            ldm4(bl, Blo + boff);
            mma_f16(acc[nt * 2], ah, bh[0], bh[2]);
            mma_f16(acc[nt * 2], ah, bl[0], bl[2]);
            mma_f16(acc[nt * 2 + 1], ah, bh[1], bh[3]);
            mma_f16(acc[nt * 2 + 1], ah, bl[1], bl[3]);
        }
    }
}

// 2-pass GEMM with A fragments in registers: acc += phA*Bh + phA*Bl
__device__ __forceinline__ void wgemm_regA(float acc[16][4], const uint32_t ph[8][4],
                                           const char* pB) {
    const f16* Bhi = (const f16*)pB;
    const f16* Blo = Bhi + PLANEE;
    int lane = threadIdx.x & 31;
    int lr = lane & 15, lc = lane >> 4;
#pragma unroll
    for (int kt = 0; kt < 8; kt++) {
#pragma unroll
        for (int nt = 0; nt < 8; nt++) {
            int boff = (nt * 16 + lr) * KP + kt * 16 + lc * 8;
            uint32_t bh[4], bl[4];
            ldm4(bh, Bhi + boff);
            ldm4(bl, Blo + boff);
            mma_f16(acc[nt * 2], ph[kt], bh[0], bh[2]);
            mma_f16(acc[nt * 2], ph[kt], bl[0], bl[2]);
            mma_f16(acc[nt * 2 + 1], ph[kt], bh[1], bh[3]);
            mma_f16(acc[nt * 2 + 1], ph[kt], bl[1], bl[3]);
        }
    }
}

// 2-pass trans-B warp GEMM (A hi only): acc[m][i] += Ah[m][r] * (Sh+Sl)[r][i]
__device__ __forceinline__ void wgemm_trans(float acc[16][4], const char* pA, const char* pS,
                                            int mrow) {
    const f16* Ahi = (const f16*)pA;
    const f16* Shi = (const f16*)pS;
    const f16* Slo = Shi + PLANEE;
    int lane = threadIdx.x & 31;
    int lr = lane & 15, lc = lane >> 4;
#pragma unroll
    for (int kt = 0; kt < 8; kt++) {
        int aoff = (mrow + lr) * KP + kt * 16 + lc * 8;
        uint32_t ah[4];
        ldm4(ah, Ahi + aoff);
#pragma unroll
        for (int nt = 0; nt < 8; nt++) {
            int boff = (kt * 16 + lr) * KP + nt * 16 + lc * 8;
            uint32_t bh[4], bl[4];
            ldm4t(bh, Shi + boff);
            ldm4t(bl, Slo + boff);
            mma_f16(acc[nt * 2], ah, bh[0], bh[1]);
            mma_f16(acc[nt * 2], ah, bl[0], bl[1]);
            mma_f16(acc[nt * 2 + 1], ah, bh[2], bh[3]);
            mma_f16(acc[nt * 2 + 1], ah, bl[2], bl[3]);
        }
    }
}

#define ZERO16x4(a)                                   \
    _Pragma("unroll") for (int _f = 0; _f < 16; _f++) \
        { a[_f][0] = 0.f; a[_f][1] = 0.f; a[_f][2] = 0.f; a[_f][3] = 0.f; }

// ---------------- kprep: fp32 -> split-fp16 images ----------------
__global__ void __launch_bounds__(256, 1)
kprep(const float* __restrict__ q, const float* __restrict__ src,
      const float* __restrict__ Wq, const float* __restrict__ Wk,
      const float* __restrict__ Wv) {
    int b = blockIdx.x;
    const float* g;
    char* dst;
    if (b < NT) { g = q + (size_t)b * 128 * C; dst = g_qimg + (size_t)b * IMG2; }
    else if (b < 2 * NT) { g = src + (size_t)(b - NT) * 128 * C; dst = g_simg + (size_t)(b - NT) * IMG2; }
    else {
        int i = b - 2 * NT;
        int mat = i >> 3, h = i & 7;
        g = ((mat == 0) ? Wq : (mat == 1) ? Wk : Wv) + (size_t)h * C * C;
        dst = g_wimg + (size_t)i * IMG2;
    }
    char* lo = dst + PLANEB;
    int tid = threadIdx.x;
#pragma unroll
    for (int it = 0; it < 8; it++) {
        int idx = tid + it * 256;
        int row = idx >> 4, c0 = (idx & 15) << 3;
        float4 a = *(const float4*)(g + (size_t)row * C + c0);
        float4 bb = *(const float4*)(g + (size_t)row * C + c0 + 4);
        float v8[8] = {a.x, a.y, a.z, a.w, bb.x, bb.y, bb.z, bb.w};
        uint32_t hw[4], lw[4];
#pragma unroll
        for (int i2 = 0; i2 < 4; i2++) {
            f16 h0 = __float2half_rn(v8[2 * i2]);
            f16 h1 = __float2half_rn(v8[2 * i2 + 1]);
            f16 l0 = __float2half_rn(v8[2 * i2] - __half2float(h0));
            f16 l1 = __float2half_rn(v8[2 * i2 + 1] - __half2float(h1));
            hw[i2] = h2pack(h0, h1);
            lw[i2] = h2pack(l0, l1);
        }
        int ob = row * 272 + c0 * 2;
        *(uint4*)(dst + ob) = make_uint4(hw[0], hw[1], hw[2], hw[3]);
        *(uint4*)(lo + ob) = make_uint4(lw[0], lw[1], lw[2], lw[3]);
    }
}

// ---------------- kw_comb: combined vss weights -> split image ----------------
__global__ void __launch_bounds__(256, 1)
kw_comb(const float* __restrict__ Wv, const float* __restrict__ Wvb,
        const float* __restrict__ vmap, const float* __restrict__ vmapb) {
    extern __shared__ char smraw[];
    float* sWb = (float*)smraw;
    int tid = threadIdx.x, lane = tid & 31, w = tid >> 5;
#pragma unroll
    for (int it = 0; it < 64; it++) {
        int idx = tid + it * 256;
        int d = idx >> 7, i = idx & 127;
        float s = 0.f;
#pragma unroll
        for (int h = 0; h < H; h++) s += Wv[((size_t)h * C + d) * C + i];
        sWb[d * PITCHF + i] = s * 0.125f;
    }
    __syncthreads();
    int o = blockIdx.x * 8 + w;
    float r[4] = {0.f, 0.f, 0.f, 0.f};
    for (int d = 0; d < 128; d++) {
        float vm = vmap[(size_t)o * C + d];
#pragma unroll
        for (int k = 0; k < 4; k++) r[k] += vm * sWb[d * PITCHF + lane + 32 * k];
    }
#pragma unroll
    for (int k = 0; k < 4; k++) storeT_p(g_WcombImg, o, lane + 32 * k, r[k]);
    if (blockIdx.x == 0 && tid < 128) {
        float s = 0.f;
        for (int d = 0; d < 128; d++) {
            float bv = 0.f;
#pragma unroll
            for (int h = 0; h < H; h++) bv += Wvb[h * C + d];
            s += vmap[(size_t)tid * C + d] * (bv * 0.125f);
        }
        g_bcomb[tid] = s + vmapb[tid];
    }
}

// ---------------- K2: per (chunk, head): phi_k -> M += phi^T src, kss ----------------
#define K2_BIA (3 * IMG2)
__global__ void __launch_bounds__(256, 1)
k2_kv(const float* __restrict__ Wkb, const float* __restrict__ ns) {
    extern __shared__ char sm[];
    char* pA = sm;               // src image (full: trans-B needs both planes)
    char* pB = sm + IMG2;        // Wk (static all subtiles)
    char* pP = sm + 2 * IMG2;    // phi^T (hi plane only used)
    float* sBk = (float*)(sm + K2_BIA);
    int chunk = blockIdx.x, h = blockIdx.y;
    int tid = threadIdx.x, w = tid >> 5, lane = tid & 31;
    int mrow = w * 16;
    int grA = mrow + (lane >> 2), grB = grA + 8;
    float ids = 1.f / (fabsf(ns[0]) + 1e-6f);

    if (tid < 128) sBk[tid] = Wkb[h * C + tid];
    float accM[16][4];
    ZERO16x4(accM);
    float kss_loc = 0.f;

    copy_img_async(pB, g_wimg + (size_t)(8 + h) * IMG2);
    copy_img_async(pA, g_simg + (size_t)(chunk * SUBT) * IMG2);
    CP_COMMIT();

    for (int s = 0; s < SUBT; s++) {
        if (s > 0) {
            __syncthreads();
            copy_img_async(pA, g_simg + (size_t)(chunk * SUBT + s) * IMG2);
            CP_COMMIT();
        }
        CP_WAIT0();
        __syncthreads();

        float acc[16][4];
        ZERO16x4(acc);
        wgemm2(acc, pA, pB, mrow);         // 2-pass (A hi only)

        float xs[16][4], s1a = 0.f, s2a = 0.f, s1b = 0.f, s2b = 0.f;
#pragma unroll
        for (int f = 0; f < 16; f++) {
            int c = ((f >> 1) << 4) + ((f & 1) << 3) + ((lane & 3) << 1);
            float b0 = sBk[c], b1 = sBk[c + 1];
            float x;
            x = (fmaxf(acc[f][0] + b0, 0.f) + 1e-6f) * ids; x *= x; xs[f][0] = x; s1a += x; s2a += x * x;
            x = (fmaxf(acc[f][1] + b1, 0.f) + 1e-6f) * ids; x *= x; xs[f][1] = x; s1a += x; s2a += x * x;
            x = (fmaxf(acc[f][2] + b0, 0.f) + 1e-6f) * ids; x *= x; xs[f][2] = x; s1b += x; s2b += x * x;
            x = (fmaxf(acc[f][3] + b1, 0.f) + 1e-6f) * ids; x *= x; xs[f][3] = x; s1b += x; s2b += x * x;
        }
        s1a += __shfl_xor_sync(~0u, s1a, 1); s1a += __shfl_xor_sync(~0u, s1a, 2);
        s2a += __shfl_xor_sync(~0u, s2a, 1); s2a += __shfl_xor_sync(~0u, s2a, 2);
        s1b += __shfl_xor_sync(~0u, s1b, 1); s1b += __shfl_xor_sync(~0u, s1b, 2);
        s2b += __shfl_xor_sync(~0u, s2b, 1); s2b += __shfl_xor_sync(~0u, s2b, 2);
        float sca = sqrtf(s1a) / (sqrtf(s2a) + 1e-8f);
        float scb = sqrtf(s1b) / (sqrtf(s2b) + 1e-8f);
#pragma unroll
        for (int f = 0; f < 16; f++) {
            int c = ((f >> 1) << 4) + ((f & 1) << 3) + ((lane & 3) << 1);
            storeT_hi(pP, c, grA, xs[f][0] * sca);
            storeT_hi(pP, c + 1, grA, xs[f][1] * sca);
            storeT_hi(pP, c, grB, xs[f][2] * scb);
            storeT_hi(pP, c + 1, grB, xs[f][3] * scb);
        }
        __syncthreads();   // phi^T hi fully visible

        if (tid < 128) {
            float s0 = 0.f;
#pragma unroll 8
            for (int r = 0; r < 128; r++)
                s0 += __half2float(*(f16*)(pP + tid * 272 + r * 2));
            kss_loc += s0;
        }
        wgemm_trans(accM, pP, pA, mrow);   // 2-pass (A hi only)
    }

    size_t base = ((size_t)(chunk * H + h)) * C * C;
#pragma unroll
    for (int f = 0; f < 16; f++) {
        int c = ((f >> 1) << 4) + ((f & 1) << 3) + ((lane & 3) << 1);
        *(float2*)(g_M_part + base + (size_t)grA * C + c) = make_float2(accM[f][0], accM[f][1]);
        *(float2*)(g_M_part + base + (size_t)grB * C + c) = make_float2(accM[f][2], accM[f][3]);
    }
    if (tid < 128)
        g_kss_part[(size_t)(chunk * H + h) * C + tid] = kss_loc;
}

// ---------------- K2b: reduce M parts -> split image; reduce kss ----------------
__global__ void k2b_reduce() {
    int i = blockIdx.x * blockDim.x + threadIdx.x;
    int h = i >> 14, rem = i & 16383, m = rem >> 7, ii = rem & 127;
    float s = 0.f;
#pragma unroll 8
    for (int c = 0; c < NC; c++) s += g_M_part[(size_t)c * (H * C * C) + i];
    storeT_p(g_Mimg + (size_t)h * IMG2, m, ii, s);
    if (i < H * C) {
        float s2 = 0.f;
#pragma unroll 8
        for (int c = 0; c < NC; c++) s2 += g_kss_part[(size_t)c * (H * C) + i];
        g_kss[i] = s2;
    }
}

// ---------------- K2c: KtV[h] = M[h] @ Wv[h]^T + kss⊗b -> split image [d][m] ----------------
__global__ void __launch_bounds__(256, 1)
k2c_ktv(const float* __restrict__ Wvb) {
    extern __shared__ char sm[];
    char* pA = sm;
    char* pB = sm + IMG2;
    float* sKss = (float*)(sm + 2 * IMG2);
    float* sBv = sKss + 128;
    int h = blockIdx.x;
    int tid = threadIdx.x, w = tid >> 5, lane = tid & 31;
    int mrow = w * 16;
    int grA = mrow + (lane >> 2), grB = grA + 8;

    copy_img_async(pA, g_Mimg + (size_t)h * IMG2);
    copy_img_async(pB, g_wimg + (size_t)(16 + h) * IMG2);
    CP_COMMIT();
    if (tid < 128) {
        sKss[tid] = g_kss[h * C + tid];
        sBv[tid] = Wvb[h * C + tid];
    }
    CP_WAIT0();
    __syncthreads();

    float acc[16][4];
    ZERO16x4(acc);
    wgemm(acc, pA, pB, mrow);   // 3-pass (tiny kernel, keep accuracy)
    float kssA = sKss[grA], kssB = sKss[grB];
    char* img = g_ktvImg + (size_t)h * IMG2;
#pragma unroll
    for (int f = 0; f < 16; f++) {
        int c = ((f >> 1) << 4) + ((f & 1) << 3) + ((lane & 3) << 1);
        storeT_p(img, c, grA, acc[f][0] + kssA * sBv[c]);
        storeT_p(img, c + 1, grA, acc[f][1] + kssA * sBv[c + 1]);
        storeT_p(img, c, grB, acc[f][2] + kssB * sBv[c]);
        storeT_p(img, c + 1, grB, acc[f][3] + kssB * sBv[c + 1]);
    }
}

// ---------------- KQ: fused phi_q + numerator + comb + epilogue ----------------
#define KQ_MISC (3 * IMG2)
__global__ void __launch_bounds__(256, 1)
kq_fused(const float* __restrict__ Wqb, const float* __restrict__ ns,
         float* __restrict__ out) {
    extern __shared__ char sm[];
    char* pA = sm;               // q hi plane (persistent), then src hi plane
    char* pB = sm + IMG2;        // Wq[h] (prefetched), then Wcomb
    char* pC = sm + 2 * IMG2;    // ktv image (prefetched)
    float* sBias = (float*)(sm + KQ_MISC);
    float* sKs = sBias + 128;
    float* sBc = sKs + 128;
    int t = blockIdx.x, n0 = t * 128;
    int tid = threadIdx.x, w = tid >> 5, lane = tid & 31;
    int mrow = w * 16;
    int grA = mrow + (lane >> 2), grB = grA + 8;
    float ids = 1.f / (fabsf(ns[0]) + 1e-6f);

    // group 1: pA(hi) + pB(0); group 2: pC(0)
    copy_plane_async(pA, g_qimg + (size_t)t * IMG2);
    copy_img_async(pB, g_wimg);
    CP_COMMIT();
    copy_img_async(pC, g_ktvImg);
    CP_COMMIT();
    if (tid < 128) sBc[tid] = g_bcomb[tid];

    float outacc[16][4];
    ZERO16x4(outacc);

    for (int h = 0; h < H; h++) {
        CP_WAIT1();        // pA + pB(h) ready (pC(h) may still be in flight)
        if (tid < 128) {
            sBias[tid] = Wqb[h * C + tid];
            sKs[tid] = g_kss[h * C + tid];
        }
        __syncthreads();

        float acc[16][4];
        ZERO16x4(acc);
        wgemm2(acc, pA, pB, mrow);         // 2-pass (A hi only)

        float xs[16][4];
        float s1a = 0.f, s2a = 0.f, sda = 0.f, s1b = 0.f, s2b = 0.f, sdb = 0.f;
#pragma unroll
        for (int f = 0; f < 16; f++) {
            int c = ((f >> 1) << 4) + ((f & 1) << 3) + ((lane & 3) << 1);
            float b0 = sBias[c], b1 = sBias[c + 1];
            float k0 = sKs[c], k1 = sKs[c + 1];
            float x;
            x = (fmaxf(acc[f][0] + b0, 0.f) + 1e-6f) * ids; x *= x; xs[f][0] = x; s1a += x; s2a += x * x; sda += x * k0;
            x = (fmaxf(acc[f][1] + b1, 0.f) + 1e-6f) * ids; x *= x; xs[f][1] = x; s1a += x; s2a += x * x; sda += x * k1;
            x = (fmaxf(acc[f][2] + b0, 0.f) + 1e-6f) * ids; x *= x; xs[f][2] = x; s1b += x; s2b += x * x; sdb += x * k0;
            x = (fmaxf(acc[f][3] + b1, 0.f) + 1e-6f) * ids; x *= x; xs[f][3] = x; s1b += x; s2b += x * x; sdb += x * k1;
        }
        s1a += __shfl_xor_sync(~0u, s1a, 1); s1a += __shfl_xor_sync(~0u, s1a, 2);
        s2a += __shfl_xor_sync(~0u, s2a, 1); s2a += __shfl_xor_sync(~0u, s2a, 2);
        sda += __shfl_xor_sync(~0u, sda, 1); sda += __shfl_xor_sync(~0u, sda, 2);
        s1b += __shfl_xor_sync(~0u, s1b, 1); s1b += __shfl_xor_sync(~0u, s1b, 2);
        s2b += __shfl_xor_sync(~0u, s2b, 1); s2b += __shfl_xor_sync(~0u, s2b, 2);
        sdb += __shfl_xor_sync(~0u, sdb, 1); sdb += __shfl_xor_sync(~0u, sdb, 2);
        float sca = sqrtf(s1a) / (sqrtf(s2a) + 1e-8f);
        float scb = sqrtf(s1b) / (sqrtf(s2b) + 1e-8f);
        float denA = 0.125f / (sca * sda + 1e-6f);
        float denB = 0.125f / (scb * sdb + 1e-6f);

        // phi -> hi A-fragments in registers (2-pass gemm2)
        uint32_t ph[8][4];
#pragma unroll
        for (int kt = 0; kt < 8; kt++) {
#pragma unroll
            for (int half = 0; half < 2; half++) {
                int f = 2 * kt + half;
                ph[kt][half * 2] = h2pack(__float2half_rn(xs[f][0] * sca),
                                          __float2half_rn(xs[f][1] * sca));
                ph[kt][half * 2 + 1] = h2pack(__float2half_rn(xs[f][2] * scb),
                                              __float2half_rn(xs[f][3] * scb));
            }
        }

        __syncthreads();   // all warps done reading pB(h)
        int hn = (h < 7) ? h + 1 : 7;
        copy_img_async(pB, g_wimg + (size_t)hn * IMG2);   // overlaps gemm2
        CP_COMMIT();
        CP_WAIT1();        // pC(h) done (pB prefetch may be pending)
        __syncthreads();   // pC visible to all warps

        // numerator GEMM: phi (regs, 2-pass) @ ktv
        ZERO16x4(acc);
        wgemm_regA(acc, ph, pC);
#pragma unroll
        for (int f = 0; f < 16; f++) {
            outacc[f][0] += acc[f][0] * denA;
            outacc[f][1] += acc[f][1] * denA;
            outacc[f][2] += acc[f][2] * denB;
            outacc[f][3] += acc[f][3] * denB;
        }
        __syncthreads();   // all warps done reading pC(h)
        if (h < 7) copy_img_async(pC, g_ktvImg + (size_t)(h + 1) * IMG2);
        else       copy_plane_async(pA, g_simg + (size_t)t * IMG2);   // src hi prefetch
        CP_COMMIT();
    }

    // comb (vss branch)
    CP_WAIT0();            // drain stray prefetches
    __syncthreads();
    copy_img_async(pB, g_WcombImg);
    CP_COMMIT();
    CP_WAIT0();
    __syncthreads();
    {
        float acc[16][4];
        ZERO16x4(acc);
        wgemm2(acc, pA, pB, mrow);         // 2-pass (A hi only)
#pragma unroll
        for (int f = 0; f < 16; f++) {
            int c = ((f >> 1) << 4) + ((f & 1) << 3) + ((lane & 3) << 1);
            outacc[f][0] += acc[f][0] + sBc[c];
            outacc[f][1] += acc[f][1] + sBc[c + 1];
            outacc[f][2] += acc[f][2] + sBc[c];
            outacc[f][3] += acc[f][3] + sBc[c + 1];
        }
    }

    // time coordinate + store
    float ssa = 0.f, ssb = 0.f;
#pragma unroll
    for (int f = 0; f < 16; f++) {
        ssa += outacc[f][0] * outacc[f][0] + outacc[f][1] * outacc[f][1];
        ssb += outacc[f][2] * outacc[f][2] + outacc[f][3] * outacc[f][3];
    }
    ssa += __shfl_xor_sync(~0u, ssa, 1); ssa += __shfl_xor_sync(~0u, ssa, 2);
    ssb += __shfl_xor_sync(~0u, ssb, 1); ssb += __shfl_xor_sync(~0u, ssb, 2);
    float* rowA = out + (size_t)(n0 + grA) * 129;
    float* rowB = out + (size_t)(n0 + grB) * 129;
    if ((lane & 3) == 0) {
        rowA[0] = sqrtf(ssa + 1.0f);
        rowB[0] = sqrtf(ssb + 1.0f);
    }
#pragma unroll
    for (int f = 0; f < 16; f++) {
        int c = ((f >> 1) << 4) + ((f & 1) << 3) + ((lane & 3) << 1);
        rowA[1 + c] = outacc[f][0];
        rowA[2 + c] = outacc[f][1];
        rowB[1 + c] = outacc[f][2];
        rowB[2 + c] = outacc[f][3];
    }
}

// ---------------- launch ----------------
extern "C" void kernel_launch(void* const* d_in, const int* in_sizes, int n_in,
                              void* d_out, int out_size) {
    const float* q     = (const float*)d_in[0];
    const float* src   = (const float*)d_in[1];
    const float* Wq    = (const float*)d_in[2];
    const float* Wqb   = (const float*)d_in[3];
    const float* Wk    = (const float*)d_in[4];
    const float* Wkb   = (const float*)d_in[5];
    const float* Wv    = (const float*)d_in[6];
    const float* Wvb   = (const float*)d_in[7];
    const float* vmap  = (const float*)d_in[8];
    const float* vmapb = (const float*)d_in[9];
    const float* ns    = (const float*)d_in[10];
    float* out = (float*)d_out;

    size_t sm2 = (size_t)3 * IMG2 + 512;           // ~209.4 KB
    size_t smc = (size_t)2 * IMG2 + 1024;          // ~140.3 KB
    size_t smq = (size_t)3 * IMG2 + 1536;          // ~210.4 KB
    size_t smw = (size_t)128 * PITCHF * 4;         // 67,584 B
    cudaFuncSetAttribute(k2_kv,    cudaFuncAttributeMaxDynamicSharedMemorySize, (int)sm2);
    cudaFuncSetAttribute(k2c_ktv,  cudaFuncAttributeMaxDynamicSharedMemorySize, (int)smc);
    cudaFuncSetAttribute(kq_fused, cudaFuncAttributeMaxDynamicSharedMemorySize, (int)smq);
    cudaFuncSetAttribute(kw_comb,  cudaFuncAttributeMaxDynamicSharedMemorySize, (int)smw);

    kprep<<<2 * NT + 24, 256>>>(q, src, Wq, Wk, Wv);
    kw_comb<<<16, 256, smw>>>(Wv, Wvb, vmap, vmapb);
    k2_kv<<<dim3(NC, H), 256, sm2>>>(Wkb, ns);
    k2b_reduce<<<(H * C * C) / 256, 256>>>();
    k2c_ktv<<<H, 256, smc>>>(Wvb);
    kq_fused<<<NT, 256, smq>>>(Wqb, ns, out);
}

// round 17
// speedup vs baseline: 1.7187x; 1.2154x over previous
#include <cuda_runtime.h>
#include <cuda_fp16.h>
#include <math.h>
#include <stdint.h>

#define NROWS 32768
#define C 128
#define H 8
#define NC 64
#define SUBT 4
#define NT (NROWS / 128)
#define KP 136                 // plane row pitch in fp16 elems (272B)
#define PLANEB 34816           // bytes per 128-row plane
#define PLANEE 17408           // elems per plane
#define IMG2 69632             // hi+lo image bytes
#define PITCHF 132

typedef __half f16;

// ---------------- scratch ----------------
__device__ float    g_M_part[NC * H * C * C];        // [c][h][m][i] fp32 partials of phi^T src
__device__ float    g_kss_part[NC * H * C];
__device__ char     g_Mimg[(size_t)H * IMG2];        // M[h] split images (row m, col i)
__device__ char     g_ktvImg[(size_t)H * IMG2];      // KtV[h] split images (row d, col m)
__device__ float    g_kss[H * C];
__device__ char     g_WcombImg[IMG2];                // Wcomb split image (row o, col i)
__device__ float    g_bcomb[C];
__device__ char     g_qimg[(size_t)NT * IMG2];
__device__ char     g_simg[(size_t)NT * IMG2];
__device__ char     g_wimg[(size_t)24 * IMG2];       // Wq[8],Wk[8],Wv[8]

// ---------------- low-level ----------------
__device__ __forceinline__ uint32_t smem_u32(const void* p) {
    return (uint32_t)__cvta_generic_to_shared(p);
}
__device__ __forceinline__ void ldm4(uint32_t r[4], const f16* p) {
    uint32_t a = smem_u32(p);
    asm volatile("ldmatrix.sync.aligned.m8n8.x4.shared.b16 {%0,%1,%2,%3}, [%4];"
                 : "=r"(r[0]), "=r"(r[1]), "=r"(r[2]), "=r"(r[3]) : "r"(a));
}
__device__ __forceinline__ void ldm4t(uint32_t r[4], const f16* p) {
    uint32_t a = smem_u32(p);
    asm volatile("ldmatrix.sync.aligned.m8n8.x4.trans.shared.b16 {%0,%1,%2,%3}, [%4];"
                 : "=r"(r[0]), "=r"(r[1]), "=r"(r[2]), "=r"(r[3]) : "r"(a));
}
__device__ __forceinline__ void mma_f16(float d[4], const uint32_t a[4],
                                        uint32_t b0, uint32_t b1) {
    asm volatile(
        "mma.sync.aligned.m16n8k16.row.col.f32.f16.f16.f32 "
        "{%0,%1,%2,%3},{%4,%5,%6,%7},{%8,%9},{%0,%1,%2,%3};"
        : "+f"(d[0]), "+f"(d[1]), "+f"(d[2]), "+f"(d[3])
        : "r"(a[0]), "r"(a[1]), "r"(a[2]), "r"(a[3]), "r"(b0), "r"(b1));
}
__device__ __forceinline__ uint32_t h2pack(f16 x, f16 y) {
    return (uint32_t)__half_as_ushort(x) | ((uint32_t)__half_as_ushort(y) << 16);
}
__device__ __forceinline__ void cpa16(uint32_t d, const void* s) {
    asm volatile("cp.async.cg.shared.global [%0], [%1], 16;" ::"r"(d), "l"(s));
}
#define CP_COMMIT() asm volatile("cp.async.commit_group;" ::: "memory")
#define CP_WAIT0()  asm volatile("cp.async.wait_group 0;" ::: "memory")
#define CP_WAIT1()  asm volatile("cp.async.wait_group 1;" ::: "memory")

// 256-thread async 68KB image copy
__device__ __forceinline__ void copy_img_async(char* dst, const char* __restrict__ src) {
    uint32_t d = smem_u32(dst);
    int tid = threadIdx.x;
#pragma unroll
    for (int it = 0; it < 17; it++) {
        int i = (tid + it * 256) * 16;
        cpa16(d + i, src + i);
    }
}
// hi-plane-only copy (34KB) for hi-only consumers
__device__ __forceinline__ void copy_plane_async(char* dst, const char* __restrict__ src) {
    uint32_t d = smem_u32(dst);
    int tid = threadIdx.x;
    for (int i = tid; i < PLANEB / 16; i += 256)
        cpa16(d + i * 16, src + i * 16);
}

// fp16 split store into hi+lo planes (plane row m, col r); works gmem/smem
__device__ __forceinline__ void storeT_p(char* p, int m, int r, float x) {
    f16 h = __float2half_rn(x);
    int ob = m * 272 + r * 2;
    *(f16*)(p + ob) = h;
    *(f16*)(p + PLANEB + ob) = __float2half_rn(x - __half2float(h));
}
// hi-plane-only store
__device__ __forceinline__ void storeT_hi(char* p, int m, int r, float x) {
    *(f16*)(p + m * 272 + r * 2) = __float2half_rn(x);
}

// 3-pass split warp GEMM (k2c only)
__device__ __forceinline__ void wgemm(float acc[16][4], const char* pA, const char* pB,
                                      int mrow) {
    const f16* Ahi = (const f16*)pA;
    const f16* Alo = Ahi + PLANEE;
    const f16* Bhi = (const f16*)pB;
    const f16* Blo = Bhi + PLANEE;
    int lane = threadIdx.x & 31;
    int lr = lane & 15, lc = lane >> 4;
#pragma unroll
    for (int kt = 0; kt < 8; kt++) {
        int aoff = (mrow + lr) * KP + kt * 16 + lc * 8;
        uint32_t ah[4], al[4];
        ldm4(ah, Ahi + aoff);
        ldm4(al, Alo + aoff);
#pragma unroll
        for (int nt = 0; nt < 8; nt++) {
            int boff = (nt * 16 + lr) * KP + kt * 16 + lc * 8;
            uint32_t bh[4], bl[4];
            ldm4(bh, Bhi + boff);
            ldm4(bl, Blo + boff);
            mma_f16(acc[nt * 2], ah, bh[0], bh[2]);
            mma_f16(acc[nt * 2], ah, bl[0], bl[2]);
            mma_f16(acc[nt * 2], al, bh[0], bh[2]);
            mma_f16(acc[nt * 2 + 1], ah, bh[1], bh[3]);
            mma_f16(acc[nt * 2 + 1], ah, bl[1], bl[3]);
            mma_f16(acc[nt * 2 + 1], al, bh[1], bh[3]);
        }
    }
}

// 1-pass warp GEMM: acc += Ah*Bh (both hi planes only)
__device__ __forceinline__ void wgemm1(float acc[16][4], const char* pA, const char* pB,
                                       int mrow) {
    const f16* Ahi = (const f16*)pA;
    const f16* Bhi = (const f16*)pB;
    int lane = threadIdx.x & 31;
    int lr = lane & 15, lc = lane >> 4;
#pragma unroll
    for (int kt = 0; kt < 8; kt++) {
        int aoff = (mrow + lr) * KP + kt * 16 + lc * 8;
        uint32_t ah[4];
        ldm4(ah, Ahi + aoff);
#pragma unroll
        for (int nt = 0; nt < 8; nt++) {
            int boff = (nt * 16 + lr) * KP + kt * 16 + lc * 8;
            uint32_t bh[4];
            ldm4(bh, Bhi + boff);
            mma_f16(acc[nt * 2], ah, bh[0], bh[2]);
            mma_f16(acc[nt * 2 + 1], ah, bh[1], bh[3]);
        }
    }
}

// 2-pass warp GEMM (A hi only): acc += Ah*Bh + Ah*Bl (comb)
__device__ __forceinline__ void wgemm2(float acc[16][4], const char* pA, const char* pB,
                                       int mrow) {
    const f16* Ahi = (const f16*)pA;
    const f16* Bhi = (const f16*)pB;
    const f16* Blo = Bhi + PLANEE;
    int lane = threadIdx.x & 31;
    int lr = lane & 15, lc = lane >> 4;
#pragma unroll
    for (int kt = 0; kt < 8; kt++) {
        int aoff = (mrow + lr) * KP + kt * 16 + lc * 8;
        uint32_t ah[4];
        ldm4(ah, Ahi + aoff);
#pragma unroll
        for (int nt = 0; nt < 8; nt++) {
            int boff = (nt * 16 + lr) * KP + kt * 16 + lc * 8;
            uint32_t bh[4], bl[4];
            ldm4(bh, Bhi + boff);
            ldm4(bl, Blo + boff);
            mma_f16(acc[nt * 2], ah, bh[0], bh[2]);
            mma_f16(acc[nt * 2], ah, bl[0], bl[2]);
            mma_f16(acc[nt * 2 + 1], ah, bh[1], bh[3]);
            mma_f16(acc[nt * 2 + 1], ah, bl[1], bl[3]);
        }
    }
}

// 2-pass GEMM with A fragments in registers: acc += phA*Bh + phA*Bl (gemm2)
__device__ __forceinline__ void wgemm_regA(float acc[16][4], const uint32_t ph[8][4],
                                           const char* pB) {
    const f16* Bhi = (const f16*)pB;
    const f16* Blo = Bhi + PLANEE;
    int lane = threadIdx.x & 31;
    int lr = lane & 15, lc = lane >> 4;
#pragma unroll
    for (int kt = 0; kt < 8; kt++) {
#pragma unroll
        for (int nt = 0; nt < 8; nt++) {
            int boff = (nt * 16 + lr) * KP + kt * 16 + lc * 8;
            uint32_t bh[4], bl[4];
            ldm4(bh, Bhi + boff);
            ldm4(bl, Blo + boff);
            mma_f16(acc[nt * 2], ph[kt], bh[0], bh[2]);
            mma_f16(acc[nt * 2], ph[kt], bl[0], bl[2]);
            mma_f16(acc[nt * 2 + 1], ph[kt], bh[1], bh[3]);
            mma_f16(acc[nt * 2 + 1], ph[kt], bl[1], bl[3]);
        }
    }
}

// 1-pass trans-B warp GEMM: acc[m][i] += Ah[m][r] * Sh[r][i]
__device__ __forceinline__ void wgemm_trans1(float acc[16][4], const char* pA, const char* pS,
                                             int mrow) {
    const f16* Ahi = (const f16*)pA;
    const f16* Shi = (const f16*)pS;
    int lane = threadIdx.x & 31;
    int lr = lane & 15, lc = lane >> 4;
#pragma unroll
    for (int kt = 0; kt < 8; kt++) {
        int aoff = (mrow + lr) * KP + kt * 16 + lc * 8;
        uint32_t ah[4];
        ldm4(ah, Ahi + aoff);
#pragma unroll
        for (int nt = 0; nt < 8; nt++) {
            int boff = (kt * 16 + lr) * KP + nt * 16 + lc * 8;
            uint32_t bh[4];
            ldm4t(bh, Shi + boff);
            mma_f16(acc[nt * 2], ah, bh[0], bh[1]);
            mma_f16(acc[nt * 2 + 1], ah, bh[2], bh[3]);
        }
    }
}

#define ZERO16x4(a)                                   \
    _Pragma("unroll") for (int _f = 0; _f < 16; _f++) \
        { a[_f][0] = 0.f; a[_f][1] = 0.f; a[_f][2] = 0.f; a[_f][3] = 0.f; }

// ---------------- kprep: fp32 -> split-fp16 images ----------------
__global__ void __launch_bounds__(256, 1)
kprep(const float* __restrict__ q, const float* __restrict__ src,
      const float* __restrict__ Wq, const float* __restrict__ Wk,
      const float* __restrict__ Wv) {
    int b = blockIdx.x;
    const float* g;
    char* dst;
    if (b < NT) { g = q + (size_t)b * 128 * C; dst = g_qimg + (size_t)b * IMG2; }
    else if (b < 2 * NT) { g = src + (size_t)(b - NT) * 128 * C; dst = g_simg + (size_t)(b - NT) * IMG2; }
    else {
        int i = b - 2 * NT;
        int mat = i >> 3, h = i & 7;
        g = ((mat == 0) ? Wq : (mat == 1) ? Wk : Wv) + (size_t)h * C * C;
        dst = g_wimg + (size_t)i * IMG2;
    }
    char* lo = dst + PLANEB;
    int tid = threadIdx.x;
#pragma unroll
    for (int it = 0; it < 8; it++) {
        int idx = tid + it * 256;
        int row = idx >> 4, c0 = (idx & 15) << 3;
        float4 a = *(const float4*)(g + (size_t)row * C + c0);
        float4 bb = *(const float4*)(g + (size_t)row * C + c0 + 4);
        float v8[8] = {a.x, a.y, a.z, a.w, bb.x, bb.y, bb.z, bb.w};
        uint32_t hw[4], lw[4];
#pragma unroll
        for (int i2 = 0; i2 < 4; i2++) {
            f16 h0 = __float2half_rn(v8[2 * i2]);
            f16 h1 = __float2half_rn(v8[2 * i2 + 1]);
            f16 l0 = __float2half_rn(v8[2 * i2] - __half2float(h0));
            f16 l1 = __float2half_rn(v8[2 * i2 + 1] - __half2float(h1));
            hw[i2] = h2pack(h0, h1);
            lw[i2] = h2pack(l0, l1);
        }
        int ob = row * 272 + c0 * 2;
        *(uint4*)(dst + ob) = make_uint4(hw[0], hw[1], hw[2], hw[3]);
        *(uint4*)(lo + ob) = make_uint4(lw[0], lw[1], lw[2], lw[3]);
    }
}

// ---------------- kw_comb: combined vss weights -> split image ----------------
__global__ void __launch_bounds__(256, 1)
kw_comb(const float* __restrict__ Wv, const float* __restrict__ Wvb,
        const float* __restrict__ vmap, const float* __restrict__ vmapb) {
    extern __shared__ char smraw[];
    float* sWb = (float*)smraw;
    int tid = threadIdx.x, lane = tid & 31, w = tid >> 5;
#pragma unroll
    for (int it = 0; it < 64; it++) {
        int idx = tid + it * 256;
        int d = idx >> 7, i = idx & 127;
        float s = 0.f;
#pragma unroll
        for (int h = 0; h < H; h++) s += Wv[((size_t)h * C + d) * C + i];
        sWb[d * PITCHF + i] = s * 0.125f;
    }
    __syncthreads();
    int o = blockIdx.x * 8 + w;
    float r[4] = {0.f, 0.f, 0.f, 0.f};
    for (int d = 0; d < 128; d++) {
        float vm = vmap[(size_t)o * C + d];
#pragma unroll
        for (int k = 0; k < 4; k++) r[k] += vm * sWb[d * PITCHF + lane + 32 * k];
    }
#pragma unroll
    for (int k = 0; k < 4; k++) storeT_p(g_WcombImg, o, lane + 32 * k, r[k]);
    if (blockIdx.x == 0 && tid < 128) {
        float s = 0.f;
        for (int d = 0; d < 128; d++) {
            float bv = 0.f;
#pragma unroll
            for (int h = 0; h < H; h++) bv += Wvb[h * C + d];
            s += vmap[(size_t)tid * C + d] * (bv * 0.125f);
        }
        g_bcomb[tid] = s + vmapb[tid];
    }
}

// ---------------- K2: per (chunk, head): phi_k -> M += phi^T src, kss ----------------
#define K2_BIA (3 * IMG2)
__global__ void __launch_bounds__(256, 1)
k2_kv(const float* __restrict__ Wkb, const float* __restrict__ ns) {
    extern __shared__ char sm[];
    char* pA = sm;               // src hi plane
    char* pB = sm + IMG2;        // Wk hi plane (static all subtiles)
    char* pP = sm + 2 * IMG2;    // phi^T hi plane
    float* sBk = (float*)(sm + K2_BIA);
    int chunk = blockIdx.x, h = blockIdx.y;
    int tid = threadIdx.x, w = tid >> 5, lane = tid & 31;
    int mrow = w * 16;
    int grA = mrow + (lane >> 2), grB = grA + 8;
    float ids = 1.f / (fabsf(ns[0]) + 1e-6f);

    if (tid < 128) sBk[tid] = Wkb[h * C + tid];
    float accM[16][4];
    ZERO16x4(accM);
    float kss_loc = 0.f;

    copy_plane_async(pB, g_wimg + (size_t)(8 + h) * IMG2);
    copy_plane_async(pA, g_simg + (size_t)(chunk * SUBT) * IMG2);
    CP_COMMIT();

    for (int s = 0; s < SUBT; s++) {
        if (s > 0) {
            __syncthreads();
            copy_plane_async(pA, g_simg + (size_t)(chunk * SUBT + s) * IMG2);
            CP_COMMIT();
        }
        CP_WAIT0();
        __syncthreads();

        float acc[16][4];
        ZERO16x4(acc);
        wgemm1(acc, pA, pB, mrow);         // 1-pass

        float xs[16][4], s1a = 0.f, s2a = 0.f, s1b = 0.f, s2b = 0.f;
#pragma unroll
        for (int f = 0; f < 16; f++) {
            int c = ((f >> 1) << 4) + ((f & 1) << 3) + ((lane & 3) << 1);
            float b0 = sBk[c], b1 = sBk[c + 1];
            float x;
            x = (fmaxf(acc[f][0] + b0, 0.f) + 1e-6f) * ids; x *= x; xs[f][0] = x; s1a += x; s2a += x * x;
            x = (fmaxf(acc[f][1] + b1, 0.f) + 1e-6f) * ids; x *= x; xs[f][1] = x; s1a += x; s2a += x * x;
            x = (fmaxf(acc[f][2] + b0, 0.f) + 1e-6f) * ids; x *= x; xs[f][2] = x; s1b += x; s2b += x * x;
            x = (fmaxf(acc[f][3] + b1, 0.f) + 1e-6f) * ids; x *= x; xs[f][3] = x; s1b += x; s2b += x * x;
        }
        s1a += __shfl_xor_sync(~0u, s1a, 1); s1a += __shfl_xor_sync(~0u, s1a, 2);
        s2a += __shfl_xor_sync(~0u, s2a, 1); s2a += __shfl_xor_sync(~0u, s2a, 2);
        s1b += __shfl_xor_sync(~0u, s1b, 1); s1b += __shfl_xor_sync(~0u, s1b, 2);
        s2b += __shfl_xor_sync(~0u, s2b, 1); s2b += __shfl_xor_sync(~0u, s2b, 2);
        float sca = sqrtf(s1a) / (sqrtf(s2a) + 1e-8f);
        float scb = sqrtf(s1b) / (sqrtf(s2b) + 1e-8f);
#pragma unroll
        for (int f = 0; f < 16; f++) {
            int c = ((f >> 1) << 4) + ((f & 1) << 3) + ((lane & 3) << 1);
            storeT_hi(pP, c, grA, xs[f][0] * sca);
            storeT_hi(pP, c + 1, grA, xs[f][1] * sca);
            storeT_hi(pP, c, grB, xs[f][2] * scb);
            storeT_hi(pP, c + 1, grB, xs[f][3] * scb);
        }
        __syncthreads();   // phi^T hi fully visible

        if (tid < 128) {
            float s0 = 0.f;
#pragma unroll 8
            for (int r = 0; r < 128; r++)
                s0 += __half2float(*(f16*)(pP + tid * 272 + r * 2));
            kss_loc += s0;
        }
        wgemm_trans1(accM, pP, pA, mrow);  // 1-pass
    }

    size_t base = ((size_t)(chunk * H + h)) * C * C;
#pragma unroll
    for (int f = 0; f < 16; f++) {
        int c = ((f >> 1) << 4) + ((f & 1) << 3) + ((lane & 3) << 1);
        *(float2*)(g_M_part + base + (size_t)grA * C + c) = make_float2(accM[f][0], accM[f][1]);
        *(float2*)(g_M_part + base + (size_t)grB * C + c) = make_float2(accM[f][2], accM[f][3]);
    }
    if (tid < 128)
        g_kss_part[(size_t)(chunk * H + h) * C + tid] = kss_loc;
}

// ---------------- K2b: reduce M parts -> split image; reduce kss ----------------
__global__ void k2b_reduce() {
    int i = blockIdx.x * blockDim.x + threadIdx.x;
    int h = i >> 14, rem = i & 16383, m = rem >> 7, ii = rem & 127;
    float s = 0.f;
#pragma unroll 8
    for (int c = 0; c < NC; c++) s += g_M_part[(size_t)c * (H * C * C) + i];
    storeT_p(g_Mimg + (size_t)h * IMG2, m, ii, s);
    if (i < H * C) {
        float s2 = 0.f;
#pragma unroll 8
        for (int c = 0; c < NC; c++) s2 += g_kss_part[(size_t)c * (H * C) + i];
        g_kss[i] = s2;
    }
}

// ---------------- K2c: KtV[h] = M[h] @ Wv[h]^T + kss⊗b -> split image [d][m] ----------------
__global__ void __launch_bounds__(256, 1)
k2c_ktv(const float* __restrict__ Wvb) {
    extern __shared__ char sm[];
    char* pA = sm;
    char* pB = sm + IMG2;
    float* sKss = (float*)(sm + 2 * IMG2);
    float* sBv = sKss + 128;
    int h = blockIdx.x;
    int tid = threadIdx.x, w = tid >> 5, lane = tid & 31;
    int mrow = w * 16;
    int grA = mrow + (lane >> 2), grB = grA + 8;

    copy_img_async(pA, g_Mimg + (size_t)h * IMG2);
    copy_img_async(pB, g_wimg + (size_t)(16 + h) * IMG2);
    CP_COMMIT();
    if (tid < 128) {
        sKss[tid] = g_kss[h * C + tid];
        sBv[tid] = Wvb[h * C + tid];
    }
    CP_WAIT0();
    __syncthreads();

    float acc[16][4];
    ZERO16x4(acc);
    wgemm(acc, pA, pB, mrow);   // 3-pass (tiny kernel, keep accuracy)
    float kssA = sKss[grA], kssB = sKss[grB];
    char* img = g_ktvImg + (size_t)h * IMG2;
#pragma unroll
    for (int f = 0; f < 16; f++) {
        int c = ((f >> 1) << 4) + ((f & 1) << 3) + ((lane & 3) << 1);
        storeT_p(img, c, grA, acc[f][0] + kssA * sBv[c]);
        storeT_p(img, c + 1, grA, acc[f][1] + kssA * sBv[c + 1]);
        storeT_p(img, c, grB, acc[f][2] + kssB * sBv[c]);
        storeT_p(img, c + 1, grB, acc[f][3] + kssB * sBv[c + 1]);
    }
}

// ---------------- KQ: fused phi_q + numerator + comb + epilogue ----------------
#define KQ_MISC (3 * IMG2)
__global__ void __launch_bounds__(256, 1)
kq_fused(const float* __restrict__ Wqb, const float* __restrict__ ns,
         float* __restrict__ out) {
    extern __shared__ char sm[];
    char* pA = sm;               // q hi plane (persistent), then src hi plane
    char* pB = sm + IMG2;        // Wq[h] hi plane (prefetched), then Wcomb full
    char* pC = sm + 2 * IMG2;    // ktv image (prefetched)
    float* sBias = (float*)(sm + KQ_MISC);
    float* sKs = sBias + 128;
    float* sBc = sKs + 128;
    int t = blockIdx.x, n0 = t * 128;
    int tid = threadIdx.x, w = tid >> 5, lane = tid & 31;
    int mrow = w * 16;
    int grA = mrow + (lane >> 2), grB = grA + 8;
    float ids = 1.f / (fabsf(ns[0]) + 1e-6f);

    // group 1: pA(hi) + pB(0,hi); group 2: pC(0)
    copy_plane_async(pA, g_qimg + (size_t)t * IMG2);
    copy_plane_async(pB, g_wimg);
    CP_COMMIT();
    copy_img_async(pC, g_ktvImg);
    CP_COMMIT();
    if (tid < 128) sBc[tid] = g_bcomb[tid];

    float outacc[16][4];
    ZERO16x4(outacc);

    for (int h = 0; h < H; h++) {
        CP_WAIT1();        // pA + pB(h) ready (pC(h) may still be in flight)
        if (tid < 128) {
            sBias[tid] = Wqb[h * C + tid];
            sKs[tid] = g_kss[h * C + tid];
        }
        __syncthreads();

        float acc[16][4];
        ZERO16x4(acc);
        wgemm1(acc, pA, pB, mrow);         // 1-pass

        float xs[16][4];
        float s1a = 0.f, s2a = 0.f, sda = 0.f, s1b = 0.f, s2b = 0.f, sdb = 0.f;
#pragma unroll
        for (int f = 0; f < 16; f++) {
            int c = ((f >> 1) << 4) + ((f & 1) << 3) + ((lane & 3) << 1);
            float b0 = sBias[c], b1 = sBias[c + 1];
            float k0 = sKs[c], k1 = sKs[c + 1];
            float x;
            x = (fmaxf(acc[f][0] + b0, 0.f) + 1e-6f) * ids; x *= x; xs[f][0] = x; s1a += x; s2a += x * x; sda += x * k0;
            x = (fmaxf(acc[f][1] + b1, 0.f) + 1e-6f) * ids; x *= x; xs[f][1] = x; s1a += x; s2a += x * x; sda += x * k1;
            x = (fmaxf(acc[f][2] + b0, 0.f) + 1e-6f) * ids; x *= x; xs[f][2] = x; s1b += x; s2b += x * x; sdb += x * k0;
            x = (fmaxf(acc[f][3] + b1, 0.f) + 1e-6f) * ids; x *= x; xs[f][3] = x; s1b += x; s2b += x * x; sdb += x * k1;
        }
        s1a += __shfl_xor_sync(~0u, s1a, 1); s1a += __shfl_xor_sync(~0u, s1a, 2);
        s2a += __shfl_xor_sync(~0u, s2a, 1); s2a += __shfl_xor_sync(~0u, s2a, 2);
        sda += __shfl_xor_sync(~0u, sda, 1); sda += __shfl_xor_sync(~0u, sda, 2);
        s1b += __shfl_xor_sync(~0u, s1b, 1); s1b += __shfl_xor_sync(~0u, s1b, 2);
        s2b += __shfl_xor_sync(~0u, s2b, 1); s2b += __shfl_xor_sync(~0u, s2b, 2);
        sdb += __shfl_xor_sync(~0u, sdb, 1); sdb += __shfl_xor_sync(~0u, sdb, 2);
        float sca = sqrtf(s1a) / (sqrtf(s2a) + 1e-8f);
        float scb = sqrtf(s1b) / (sqrtf(s2b) + 1e-8f);
        float denA = 0.125f / (sca * sda + 1e-6f);
        float denB = 0.125f / (scb * sdb + 1e-6f);

        // phi -> hi A-fragments in registers (2-pass gemm2)
        uint32_t ph[8][4];
#pragma unroll
        for (int kt = 0; kt < 8; kt++) {
#pragma unroll
            for (int half = 0; half < 2; half++) {
                int f = 2 * kt + half;
                ph[kt][half * 2] = h2pack(__float2half_rn(xs[f][0] * sca),
                                          __float2half_rn(xs[f][1] * sca));
                ph[kt][half * 2 + 1] = h2pack(__float2half_rn(xs[f][2] * scb),
                                              __float2half_rn(xs[f][3] * scb));
            }
        }

        __syncthreads();   // all warps done reading pB(h)
        int hn = (h < 7) ? h + 1 : 7;
        copy_plane_async(pB, g_wimg + (size_t)hn * IMG2);   // overlaps gemm2
        CP_COMMIT();
        CP_WAIT1();        // pC(h) done (pB prefetch may be pending)
        __syncthreads();   // pC visible to all warps

        // numerator GEMM: phi (regs, 2-pass) @ ktv
        ZERO16x4(acc);
        wgemm_regA(acc, ph, pC);
#pragma unroll
        for (int f = 0; f < 16; f++) {
            outacc[f][0] += acc[f][0] * denA;
            outacc[f][1] += acc[f][1] * denA;
            outacc[f][2] += acc[f][2] * denB;
            outacc[f][3] += acc[f][3] * denB;
        }
        __syncthreads();   // all warps done reading pC(h)
        if (h < 7) copy_img_async(pC, g_ktvImg + (size_t)(h + 1) * IMG2);
        else       copy_plane_async(pA, g_simg + (size_t)t * IMG2);   // src hi prefetch
        CP_COMMIT();
    }

    // comb (vss branch)
    CP_WAIT0();            // drain stray prefetches
    __syncthreads();
    copy_img_async(pB, g_WcombImg);
    CP_COMMIT();
    CP_WAIT0();
    __syncthreads();
    {
        float acc[16][4];
        ZERO16x4(acc);
        wgemm2(acc, pA, pB, mrow);         // 2-pass (A hi only)
#pragma unroll
        for (int f = 0; f < 16; f++) {
            int c = ((f >> 1) << 4) + ((f & 1) << 3) + ((lane & 3) << 1);
            outacc[f][0] += acc[f][0] + sBc[c];
            outacc[f][1] += acc[f][1] + sBc[c + 1];
            outacc[f][2] += acc[f][2] + sBc[c];
            outacc[f][3] += acc[f][3] + sBc[c + 1];
        }
    }

    // time coordinate + store
    float ssa = 0.f, ssb = 0.f;
#pragma unroll
    for (int f = 0; f < 16; f++) {
        ssa += outacc[f][0] * outacc[f][0] + outacc[f][1] * outacc[f][1];
        ssb += outacc[f][2] * outacc[f][2] + outacc[f][3] * outacc[f][3];
    }
    ssa += __shfl_xor_sync(~0u, ssa, 1); ssa += __shfl_xor_sync(~0u, ssa, 2);
    ssb += __shfl_xor_sync(~0u, ssb, 1); ssb += __shfl_xor_sync(~0u, ssb, 2);
    float* rowA = out + (size_t)(n0 + grA) * 129;
    float* rowB = out + (size_t)(n0 + grB) * 129;
    if ((lane & 3) == 0) {
        rowA[0] = sqrtf(ssa + 1.0f);
        rowB[0] = sqrtf(ssb + 1.0f);
    }
#pragma unroll
    for (int f = 0; f < 16; f++) {
        int c = ((f >> 1) << 4) + ((f & 1) << 3) + ((lane & 3) << 1);
        rowA[1 + c] = outacc[f][0];
        rowA[2 + c] = outacc[f][1];
        rowB[1 + c] = outacc[f][2];
        rowB[2 + c] = outacc[f][3];
    }
}

// ---------------- launch ----------------
extern "C" void kernel_launch(void* const* d_in, const int* in_sizes, int n_in,
                              void* d_out, int out_size) {
    const float* q     = (const float*)d_in[0];
    const float* src   = (const float*)d_in[1];
    const float* Wq    = (const float*)d_in[2];
    const float* Wqb   = (const float*)d_in[3];
    const float* Wk    = (const float*)d_in[4];
    const float* Wkb   = (const float*)d_in[5];
    const float* Wv    = (const float*)d_in[6];
    const float* Wvb   = (const float*)d_in[7];
    const float* vmap  = (const float*)d_in[8];
    const float* vmapb = (const float*)d_in[9];
    const float* ns    = (const float*)d_in[10];
    float* out = (float*)d_out;

    size_t sm2 = (size_t)3 * IMG2 + 512;           // ~209.4 KB
    size_t smc = (size_t)2 * IMG2 + 1024;          // ~140.3 KB
    size_t smq = (size_t)3 * IMG2 + 1536;          // ~210.4 KB
    size_t smw = (size_t)128 * PITCHF * 4;         // 67,584 B
    cudaFuncSetAttribute(k2_kv,    cudaFuncAttributeMaxDynamicSharedMemorySize, (int)sm2);
    cudaFuncSetAttribute(k2c_ktv,  cudaFuncAttributeMaxDynamicSharedMemorySize, (int)smc);
    cudaFuncSetAttribute(kq_fused, cudaFuncAttributeMaxDynamicSharedMemorySize, (int)smq);
    cudaFuncSetAttribute(kw_comb,  cudaFuncAttributeMaxDynamicSharedMemorySize, (int)smw);

    kprep<<<2 * NT + 24, 256>>>(q, src, Wq, Wk, Wv);
    kw_comb<<<16, 256, smw>>>(Wv, Wvb, vmap, vmapb);
    k2_kv<<<dim3(NC, H), 256, sm2>>>(Wkb, ns);
    k2b_reduce<<<(H * C * C) / 256, 256>>>();
    k2c_ktv<<<H, 256, smc>>>(Wvb);
    kq_fused<<<NT, 256, smq>>>(Wqb, ns, out);
}